// round 1
// baseline (speedup 1.0000x reference)
#include <cuda_runtime.h>
#include <math.h>

#define NB 4
#define NL 4096
#define NC 1024
#define NH 8
#define NR 512
#define ND 64
#define LAMBDA_INIT 0.8f
#define EPS 1e-6f

// ---------------- device scratch (no allocations allowed) ----------------
__device__ float g_xd  [NB*NR*NC];        // downsampled x       (B, r, C)
__device__ float g_q   [NB*NR*NC];        // xd @ Wq^T
__device__ float g_k   [NB*NR*NC];
__device__ float g_v   [NB*NR*NC];
__device__ float g_q1  [NB*NH*NR*ND];     // (b,h,i,d)
__device__ float g_q2  [NB*NH*NR*ND];
__device__ float g_k1  [NB*NH*NR*ND];
__device__ float g_k2  [NB*NH*NR*ND];
__device__ float g_vt  [NB*NH*2*ND*NR];   // (b,h,c[128],i) -> NT layout for PV gemm
__device__ float g_s1  [NB*NH*NR*NR];     // scores1 / combined probs
__device__ float g_s2  [NB*NH*NR*NR];     // scores2
__device__ float g_diff[NB*NH*NR*2*ND];   // (b,h,i,128)
__device__ float g_y   [NB*NR*NC];        // head-normed, reshaped (B,r,C)
__device__ float g_lam [1];

// ---------------- generic batched NT GEMM: C[m,n] = alpha * sum_k A[m,k]*B[n,k] ----
// Requires M%BM==0, N%BN==0, K%BK==0 (true for all call sites here).
template<int BM, int BN, int BK>
__global__ __launch_bounds__(256)
void gemm_nt_kernel(const float* __restrict__ A, const float* __restrict__ Bm,
                    float* __restrict__ Cm, int M, int N, int K,
                    long long sA, long long sB, long long sC,
                    float alpha, int fuse_silu)
{
    __shared__ float As[BK][BM];
    __shared__ float Bs[BK][BN];
    const float* Ab = A  + (long long)blockIdx.z * sA;
    const float* Bb = Bm + (long long)blockIdx.z * sB;
    float*       Cb = Cm + (long long)blockIdx.z * sC;
    const int bm = blockIdx.y * BM;
    const int bn = blockIdx.x * BN;
    const int tid = threadIdx.x;
    const int tm = (tid >> 4) << 3;   // 16x16 thread grid, 8x8 micro tile
    const int tn = (tid & 15) << 3;

    float acc[8][8];
    #pragma unroll
    for (int i = 0; i < 8; i++)
        #pragma unroll
        for (int j = 0; j < 8; j++) acc[i][j] = 0.f;

    for (int k0 = 0; k0 < K; k0 += BK) {
        #pragma unroll
        for (int it = 0; it < (BM*BK)/(256*4); it++) {
            int idx = tid + it*256;
            int row = idx >> 2;
            int c4  = idx & 3;
            float4 t = *(const float4*)(Ab + (long long)(bm+row)*K + k0 + (c4<<2));
            As[(c4<<2)+0][row] = t.x;
            As[(c4<<2)+1][row] = t.y;
            As[(c4<<2)+2][row] = t.z;
            As[(c4<<2)+3][row] = t.w;
        }
        #pragma unroll
        for (int it = 0; it < (BN*BK)/(256*4); it++) {
            int idx = tid + it*256;
            int row = idx >> 2;
            int c4  = idx & 3;
            float4 t = *(const float4*)(Bb + (long long)(bn+row)*K + k0 + (c4<<2));
            Bs[(c4<<2)+0][row] = t.x;
            Bs[(c4<<2)+1][row] = t.y;
            Bs[(c4<<2)+2][row] = t.z;
            Bs[(c4<<2)+3][row] = t.w;
        }
        __syncthreads();
        #pragma unroll
        for (int kk = 0; kk < BK; kk++) {
            float4 a0 = *(const float4*)&As[kk][tm];
            float4 a1 = *(const float4*)&As[kk][tm+4];
            float4 b0 = *(const float4*)&Bs[kk][tn];
            float4 b1 = *(const float4*)&Bs[kk][tn+4];
            float av[8] = {a0.x,a0.y,a0.z,a0.w,a1.x,a1.y,a1.z,a1.w};
            float bv[8] = {b0.x,b0.y,b0.z,b0.w,b1.x,b1.y,b1.z,b1.w};
            #pragma unroll
            for (int i = 0; i < 8; i++)
                #pragma unroll
                for (int j = 0; j < 8; j++)
                    acc[i][j] += av[i]*bv[j];
        }
        __syncthreads();
    }

    #pragma unroll
    for (int i = 0; i < 8; i++) {
        #pragma unroll
        for (int j4 = 0; j4 < 2; j4++) {
            float4 o;
            float vals[4];
            #pragma unroll
            for (int j = 0; j < 4; j++) {
                float vv = acc[i][j4*4+j]*alpha;
                if (fuse_silu) vv = vv / (1.f + expf(-vv));
                vals[j] = vv;
            }
            o.x = vals[0]; o.y = vals[1]; o.z = vals[2]; o.w = vals[3];
            *(float4*)(Cb + (long long)(bm+tm+i)*N + bn+tn + j4*4) = o;
        }
    }
}

// ---------------- downsample: xd[b,i,c] = 0.5*(x[b,8i+3,c]+x[b,8i+4,c]) --------
__global__ void downsample_kernel(const float4* __restrict__ x, float4* __restrict__ xd)
{
    int idx = blockIdx.x*blockDim.x + threadIdx.x;
    if (idx >= NB*NR*NC/4) return;
    int c4 = idx & 255;
    int bi = idx >> 8;
    int i  = bi & (NR-1);
    int b  = bi >> 9;
    long long row = (long long)b*NL + 8*i + 3;
    float4 p = x[row*256 + c4];
    float4 q = x[(row+1)*256 + c4];
    float4 o;
    o.x = 0.5f*(p.x+q.x); o.y = 0.5f*(p.y+q.y);
    o.z = 0.5f*(p.z+q.z); o.w = 0.5f*(p.w+q.w);
    xd[idx] = o;
}

// ---------------- rmsnorm(d=64) + rope(pos = head index!) for q and k ----------
// input row layout: row = ((b*R+i)*H + h)*2 + s, 64 contiguous floats
// output: (b,h,i,d) contiguous
__global__ void normrope_kernel(const float* __restrict__ qb, const float* __restrict__ kb,
                                const float* __restrict__ qw, const float* __restrict__ kw,
                                float* __restrict__ q1, float* __restrict__ q2,
                                float* __restrict__ k1, float* __restrict__ k2)
{
    int gw   = (blockIdx.x*blockDim.x + threadIdx.x) >> 5;
    int lane = threadIdx.x & 31;
    const int NROWS = NB*NR*NH*2;
    if (gw >= 2*NROWS) return;
    int isK = gw >= NROWS;
    int row = isK ? (gw - NROWS) : gw;
    const float* src = (isK ? kb : qb) + (long long)row * 64;
    float x1 = src[lane];
    float x2 = src[lane+32];
    float ss = x1*x1 + x2*x2;
    #pragma unroll
    for (int o = 16; o; o >>= 1) ss += __shfl_xor_sync(0xffffffffu, ss, o);
    float inv = 1.f / sqrtf(ss*(1.f/64.f) + EPS);
    const float* w = isK ? kw : qw;
    float n1 = x1*inv*w[lane];
    float n2 = x2*inv*w[lane+32];
    int s  = row & 1;
    int h  = (row >> 1) & 7;
    int bi = row >> 4;
    int b  = bi >> 9;
    int i  = bi & 511;
    // rope: position is the HEAD index h (reference quirk)
    float f = powf(10000.f, -(float)lane * (1.f/32.f));
    float ang = (float)h * f;
    float sn, cs;
    sincosf(ang, &sn, &cs);
    float o1 = n1*cs - n2*sn;
    float o2 = n1*sn + n2*cs;
    float* dst = isK ? (s ? k2 : k1) : (s ? q2 : q1);
    long long off = ((long long)((b*NH + h)*NR) + i) * 64;
    dst[off + lane]      = o1;
    dst[off + lane + 32] = o2;
}

// ---------------- v transpose to (b,h,c,i) for NT PV gemm ----------------------
__global__ void vtrans_kernel(const float* __restrict__ v, float* __restrict__ vt)
{
    int idx = blockIdx.x*blockDim.x + threadIdx.x;
    if (idx >= NB*NH*128*NR) return;
    int i  = idx & 511;
    int c  = (idx >> 9) & 127;
    int bh = idx >> 16;
    int b  = bh >> 3;
    int h  = bh & 7;
    vt[idx] = v[((long long)(b*NR + i))*NC + h*128 + c];
}

// ---------------- lambda scalar -----------------------------------------------
__global__ void lambda_kernel(const float* lq1, const float* lk1,
                              const float* lq2, const float* lk2, float* out)
{
    int t = threadIdx.x; // 32 threads
    float a = lq1[t]*lk1[t] + lq1[t+32]*lk1[t+32];
    float b = lq2[t]*lk2[t] + lq2[t+32]*lk2[t+32];
    #pragma unroll
    for (int o = 16; o; o >>= 1) {
        a += __shfl_xor_sync(0xffffffffu, a, o);
        b += __shfl_xor_sync(0xffffffffu, b, o);
    }
    if (t == 0) out[0] = expf(a) - expf(b) + LAMBDA_INIT;
}

// ---------------- dual softmax + combine: p = softmax(s1) - lam*softmax(s2) ----
// one warp per 512-wide row, in-place into s1
__global__ void softmax_combine_kernel(float* __restrict__ s1, const float* __restrict__ s2,
                                       const float* __restrict__ lamp)
{
    int gw   = (blockIdx.x*blockDim.x + threadIdx.x) >> 5;
    int lane = threadIdx.x & 31;
    if (gw >= NB*NH*NR) return;
    float4* r1 = (float4*)(s1 + (long long)gw * NR);
    const float4* r2 = (const float4*)(s2 + (long long)gw * NR);
    float4 v1[4], v2[4];
    float m1 = -1e30f, m2 = -1e30f;
    #pragma unroll
    for (int i = 0; i < 4; i++) {
        v1[i] = r1[lane + 32*i];
        v2[i] = r2[lane + 32*i];
        m1 = fmaxf(m1, fmaxf(fmaxf(v1[i].x, v1[i].y), fmaxf(v1[i].z, v1[i].w)));
        m2 = fmaxf(m2, fmaxf(fmaxf(v2[i].x, v2[i].y), fmaxf(v2[i].z, v2[i].w)));
    }
    #pragma unroll
    for (int o = 16; o; o >>= 1) {
        m1 = fmaxf(m1, __shfl_xor_sync(0xffffffffu, m1, o));
        m2 = fmaxf(m2, __shfl_xor_sync(0xffffffffu, m2, o));
    }
    float s1sum = 0.f, s2sum = 0.f;
    #pragma unroll
    for (int i = 0; i < 4; i++) {
        v1[i].x = expf(v1[i].x - m1); v1[i].y = expf(v1[i].y - m1);
        v1[i].z = expf(v1[i].z - m1); v1[i].w = expf(v1[i].w - m1);
        v2[i].x = expf(v2[i].x - m2); v2[i].y = expf(v2[i].y - m2);
        v2[i].z = expf(v2[i].z - m2); v2[i].w = expf(v2[i].w - m2);
        s1sum += v1[i].x + v1[i].y + v1[i].z + v1[i].w;
        s2sum += v2[i].x + v2[i].y + v2[i].z + v2[i].w;
    }
    #pragma unroll
    for (int o = 16; o; o >>= 1) {
        s1sum += __shfl_xor_sync(0xffffffffu, s1sum, o);
        s2sum += __shfl_xor_sync(0xffffffffu, s2sum, o);
    }
    float lam = lamp[0];
    float is1 = 1.f / s1sum;
    float is2 = lam / s2sum;
    #pragma unroll
    for (int i = 0; i < 4; i++) {
        float4 o;
        o.x = v1[i].x*is1 - v2[i].x*is2;
        o.y = v1[i].y*is1 - v2[i].y*is2;
        o.z = v1[i].z*is1 - v2[i].z*is2;
        o.w = v1[i].w*is1 - v2[i].w*is2;
        r1[lane + 32*i] = o;
    }
}

// ---------------- head rmsnorm(128) * 0.2 -> (B,r,C) layout -------------------
__global__ void headnorm_kernel(const float* __restrict__ diff, const float* __restrict__ hw,
                                float* __restrict__ y)
{
    int gw   = (blockIdx.x*blockDim.x + threadIdx.x) >> 5;
    int lane = threadIdx.x & 31;
    if (gw >= NB*NH*NR) return;
    const float4* src = (const float4*)(diff + (long long)gw * 128);
    float4 a = src[lane];
    float ss = a.x*a.x + a.y*a.y + a.z*a.z + a.w*a.w;
    #pragma unroll
    for (int o = 16; o; o >>= 1) ss += __shfl_xor_sync(0xffffffffu, ss, o);
    float inv = (1.f - LAMBDA_INIT) / sqrtf(ss*(1.f/128.f) + EPS);
    int bh = gw >> 9;
    int i  = gw & 511;
    int b  = bh >> 3;
    int h  = bh & 7;
    float4 w = ((const float4*)hw)[lane];
    float4 o;
    o.x = a.x*inv*w.x; o.y = a.y*inv*w.y; o.z = a.z*inv*w.z; o.w = a.w*inv*w.w;
    ((float4*)(y + ((long long)(b*NR + i))*NC + h*128))[lane] = o;
}

// ---------------- upsample 512 -> 4096 ----------------------------------------
__global__ void upsample_kernel(const float4* __restrict__ lr, float4* __restrict__ out)
{
    int idx = blockIdx.x*blockDim.x + threadIdx.x;
    if (idx >= NB*NL*NC/4) return;
    int c4 = idx & 255;
    int j  = (idx >> 8) & (NL-1);
    int b  = idx >> 20;
    float coords = fminf(fmaxf(((float)j + 0.5f)*0.125f - 0.5f, 0.f), 511.f);
    int lo = (int)coords;
    int hi = min(lo + 1, 511);
    float w  = coords - (float)lo;
    float w0 = 1.f - w;
    long long base = (long long)b * NR * 256;
    float4 a = lr[base + (long long)lo*256 + c4];
    float4 c = lr[base + (long long)hi*256 + c4];
    float4 o;
    o.x = a.x*w0 + c.x*w; o.y = a.y*w0 + c.y*w;
    o.z = a.z*w0 + c.z*w; o.w = a.w*w0 + c.w*w;
    out[idx] = o;
}

// ---------------- host launcher -----------------------------------------------
extern "C" void kernel_launch(void* const* d_in, const int* in_sizes, int n_in,
                              void* d_out, int out_size)
{
    const float* x   = (const float*)d_in[0];
    const float* Wq  = (const float*)d_in[1];
    const float* Wk  = (const float*)d_in[2];
    const float* Wv  = (const float*)d_in[3];
    const float* Wo  = (const float*)d_in[4];
    const float* qw  = (const float*)d_in[5];
    const float* kw  = (const float*)d_in[6];
    const float* hw  = (const float*)d_in[7];
    const float* lq1 = (const float*)d_in[8];
    const float* lk1 = (const float*)d_in[9];
    const float* lq2 = (const float*)d_in[10];
    const float* lk2 = (const float*)d_in[11];

    float* full_out = (float*)d_out;                       // (B, L, C)
    float* lowrank  = full_out + (size_t)NB*NL*NC;         // (B, r, C)

    float *xd,*q,*k,*v,*q1,*q2,*k1,*k2,*vt,*s1,*s2,*diff,*y,*lam;
    cudaGetSymbolAddress((void**)&xd,   g_xd);
    cudaGetSymbolAddress((void**)&q,    g_q);
    cudaGetSymbolAddress((void**)&k,    g_k);
    cudaGetSymbolAddress((void**)&v,    g_v);
    cudaGetSymbolAddress((void**)&q1,   g_q1);
    cudaGetSymbolAddress((void**)&q2,   g_q2);
    cudaGetSymbolAddress((void**)&k1,   g_k1);
    cudaGetSymbolAddress((void**)&k2,   g_k2);
    cudaGetSymbolAddress((void**)&vt,   g_vt);
    cudaGetSymbolAddress((void**)&s1,   g_s1);
    cudaGetSymbolAddress((void**)&s2,   g_s2);
    cudaGetSymbolAddress((void**)&diff, g_diff);
    cudaGetSymbolAddress((void**)&y,    g_y);
    cudaGetSymbolAddress((void**)&lam,  g_lam);

    // 1. downsample
    downsample_kernel<<<(NB*NR*NC/4 + 255)/256, 256>>>((const float4*)x, (float4*)xd);

    // 2. QKV projections (M=2048, N=1024, K=1024)
    dim3 gqkv(NC/128, (NB*NR)/128, 1);
    gemm_nt_kernel<128,128,16><<<gqkv, 256>>>(xd, Wq, q, NB*NR, NC, NC, 0,0,0, 1.f, 0);
    gemm_nt_kernel<128,128,16><<<gqkv, 256>>>(xd, Wk, k, NB*NR, NC, NC, 0,0,0, 1.f, 0);
    gemm_nt_kernel<128,128,16><<<gqkv, 256>>>(xd, Wv, v, NB*NR, NC, NC, 0,0,0, 1.f, 0);

    // 3. rmsnorm + rope (q & k), v transpose, lambda (all independent)
    normrope_kernel<<<(2*NB*NR*NH*2*32 + 255)/256, 256>>>(q, k, qw, kw, q1, q2, k1, k2);
    vtrans_kernel<<<(NB*NH*128*NR + 255)/256, 256>>>(v, vt);
    lambda_kernel<<<1, 32>>>(lq1, lk1, lq2, lk2, lam);

    // 4. attention scores (batched M=512,N=512,K=64, alpha = d^-0.5)
    dim3 gsc(NR/128, NR/128, NB*NH);
    gemm_nt_kernel<128,128,16><<<gsc, 256>>>(q1, k1, s1, NR, NR, ND,
        (long long)NR*ND, (long long)NR*ND, (long long)NR*NR, 0.125f, 0);
    gemm_nt_kernel<128,128,16><<<gsc, 256>>>(q2, k2, s2, NR, NR, ND,
        (long long)NR*ND, (long long)NR*ND, (long long)NR*NR, 0.125f, 0);

    // 5. dual softmax + combine (in-place into s1)
    softmax_combine_kernel<<<(NB*NH*NR*32 + 255)/256, 256>>>(s1, s2, lam);

    // 6. PV: diff = p @ v   (batched M=512, N=128, K=512)
    dim3 gpv(128/128, NR/128, NB*NH);
    gemm_nt_kernel<128,128,16><<<gpv, 256>>>(s1, vt, diff, NR, 128, NR,
        (long long)NR*NR, (long long)128*NR, (long long)NR*128, 1.f, 0);

    // 7. head rmsnorm * (1-lambda_init) -> (B,r,C)
    headnorm_kernel<<<(NB*NH*NR*32 + 255)/256, 256>>>(diff, hw, y);

    // 8. Wo projection + fused silu -> lowrank_out (second output)
    gemm_nt_kernel<128,128,16><<<gqkv, 256>>>(y, Wo, lowrank, NB*NR, NC, NC, 0,0,0, 1.f, 1);

    // 9. upsample 512 -> 4096 -> full_out (first output)
    upsample_kernel<<<(NB*NL*NC/4 + 255)/256, 256>>>((const float4*)lowrank, (float4*)full_out);
}

// round 3
// speedup vs baseline: 2.2005x; 2.2005x over previous
#include <cuda_runtime.h>
#include <cuda_bf16.h>
#include <math.h>
#include <stdint.h>

#define NB 4
#define NL 4096
#define NC 1024
#define NH 8
#define NR 512
#define ND 64
#define LAMBDA_INIT 0.8f
#define EPS 1e-6f

// ======================= device scratch (no allocs allowed) ==================
__device__ __nv_bfloat16 g_xdh[NB*NR*NC], g_xdl[NB*NR*NC];
__device__ __nv_bfloat16 g_Wqh[NC*NC], g_Wql[NC*NC];
__device__ __nv_bfloat16 g_Wkh[NC*NC], g_Wkl[NC*NC];
__device__ __nv_bfloat16 g_Wvh[NC*NC], g_Wvl[NC*NC];
__device__ __nv_bfloat16 g_Woh[NC*NC], g_Wol[NC*NC];
__device__ float g_q[NB*NR*NC], g_k[NB*NR*NC], g_v[NB*NR*NC];
__device__ __nv_bfloat16 g_q1h[NB*NH*NR*ND], g_q1l[NB*NH*NR*ND];
__device__ __nv_bfloat16 g_q2h[NB*NH*NR*ND], g_q2l[NB*NH*NR*ND];
__device__ __nv_bfloat16 g_k1h[NB*NH*NR*ND], g_k1l[NB*NH*NR*ND];
__device__ __nv_bfloat16 g_k2h[NB*NH*NR*ND], g_k2l[NB*NH*NR*ND];
__device__ __nv_bfloat16 g_vth[NB*NH*128*NR], g_vtl[NB*NH*128*NR];
__device__ float g_s1[NB*NH*NR*NR], g_s2[NB*NH*NR*NR];
__device__ __nv_bfloat16 g_ph[NB*NH*NR*NR], g_pl[NB*NH*NR*NR];
__device__ float g_diff[NB*NH*NR*128];
__device__ __nv_bfloat16 g_yh[NB*NR*NC], g_yl[NB*NR*NC];
__device__ float g_lam[1];

// ======================= cp.async helpers (sm_80 baseline, no 'a' feats) =====
__device__ __forceinline__ uint32_t smem_u32(const void* p){
    uint32_t a;
    asm("{ .reg .u64 t; cvta.to.shared.u64 t, %1; cvt.u32.u64 %0, t; }" : "=r"(a) : "l"(p));
    return a;
}
__device__ __forceinline__ void cpa16(uint32_t d, const void* s){
    asm volatile("cp.async.cg.shared.global [%0], [%1], 16;" :: "r"(d), "l"(s));
}
#define CP_COMMIT() asm volatile("cp.async.commit_group;" ::: "memory")
#define CP_WAIT0()  asm volatile("cp.async.wait_group 0;" ::: "memory")
#define CP_WAIT1()  asm volatile("cp.async.wait_group 1;" ::: "memory")

__device__ __forceinline__ void mma16816(float* c,
    uint32_t a0, uint32_t a1, uint32_t a2, uint32_t a3, uint32_t b0, uint32_t b1)
{
    asm volatile(
        "mma.sync.aligned.m16n8k16.row.col.f32.bf16.bf16.f32 "
        "{%0,%1,%2,%3}, {%4,%5,%6,%7}, {%8,%9}, {%0,%1,%2,%3};"
        : "+f"(c[0]), "+f"(c[1]), "+f"(c[2]), "+f"(c[3])
        : "r"(a0), "r"(a1), "r"(a2), "r"(a3), "r"(b0), "r"(b1));
}

// ======================= HMMA split-bf16 batched NT GEMM =====================
// C[m,n] = alpha * sum_k (Ah+Al)[m,k]*(Bh+Bl)[n,k]   (Al*Bl dropped)
// CTA tile 128x128, BK=32, 8 warps (2 x 4), warp tile 64x32.
// smem tile: 128 rows x 80B (64B data + 16B pad -> conflict-free LDS pattern)
#define ROW_B   80
#define TILE_B  (128*ROW_B)          // 10240
#define STG_B   (4*TILE_B)           // Ah,Al,Bh,Bl = 40960
#define GEMM_SMEM (2*STG_B)          // 81920

__device__ __forceinline__ void ld_stage(uint32_t sbase, int tid, long long c32,
    const __nv_bfloat16* Ahb, const __nv_bfloat16* Alb,
    const __nv_bfloat16* Bhb, const __nv_bfloat16* Blb, int K)
{
    int seg = tid & 3;
    #pragma unroll
    for (int it = 0; it < 8; it++) {
        int i = tid + it*256;
        int r = (i >> 2) & 127;
        const __nv_bfloat16* src =
            (it < 2) ? Ahb : (it < 4) ? Alb : (it < 6) ? Bhb : Blb;
        cpa16(sbase + (it >> 1)*TILE_B + r*ROW_B + seg*16,
              src + (long long)r*K + c32 + seg*8);
    }
    CP_COMMIT();
}

__global__ __launch_bounds__(256, 1)
void gemm_mma(const __nv_bfloat16* __restrict__ Ah, const __nv_bfloat16* __restrict__ Al,
              const __nv_bfloat16* __restrict__ Bh, const __nv_bfloat16* __restrict__ Bl,
              float* __restrict__ C, int M, int N, int K,
              long long sA, long long sB, long long sC, float alpha, int silu)
{
    extern __shared__ char sm[];
    uint32_t sb = smem_u32(sm);
    const int tid  = threadIdx.x;
    const int wid  = tid >> 5, lane = tid & 31;
    const int gid  = lane >> 2, tig = lane & 3;
    const int wm   = (wid & 1) * 64;       // warp row offset in CTA tile
    const int wn   = (wid >> 1) * 32;      // warp col offset
    const int bm   = blockIdx.y * 128, bn = blockIdx.x * 128;

    const __nv_bfloat16* Ahb = Ah + blockIdx.z*sA + (long long)bm*K;
    const __nv_bfloat16* Alb = Al + blockIdx.z*sA + (long long)bm*K;
    const __nv_bfloat16* Bhb = Bh + blockIdx.z*sB + (long long)bn*K;
    const __nv_bfloat16* Blb = Bl + blockIdx.z*sB + (long long)bn*K;
    float* Cb = C + blockIdx.z*sC;

    float acc[4][4][4];
    #pragma unroll
    for (int mi = 0; mi < 4; mi++)
        #pragma unroll
        for (int ni = 0; ni < 4; ni++)
            #pragma unroll
            for (int t = 0; t < 4; t++) acc[mi][ni][t] = 0.f;

    const int nch = K >> 5;
    ld_stage(sb, tid, 0, Ahb, Alb, Bhb, Blb, K);

    for (int c = 0; c < nch; c++) {
        if (c + 1 < nch) {
            ld_stage(sb + ((c + 1) & 1)*STG_B, tid, (long long)(c + 1)*32,
                     Ahb, Alb, Bhb, Blb, K);
            CP_WAIT1();
        } else {
            CP_WAIT0();
        }
        __syncthreads();

        const char* p  = sm + (c & 1)*STG_B;
        const char* pAh = p;
        const char* pAl = p + TILE_B;
        const char* pBh = p + 2*TILE_B;
        const char* pBl = p + 3*TILE_B;
        const int abase = (wm + gid)*ROW_B + tig*4;
        const int bbase = (wn + gid)*ROW_B + tig*4;

        #pragma unroll
        for (int kk = 0; kk < 2; kk++) {            // two k16 steps per BK=32
            const int ko = kk*32;                   // 16 cols * 2B
            uint32_t ah[4][4], al[4][4], bh[4][2], bl[4][2];
            #pragma unroll
            for (int mi = 0; mi < 4; mi++) {
                const char* q0 = pAh + abase + mi*16*ROW_B + ko;
                ah[mi][0] = *(const uint32_t*)(q0);
                ah[mi][1] = *(const uint32_t*)(q0 + 8*ROW_B);
                ah[mi][2] = *(const uint32_t*)(q0 + 16);
                ah[mi][3] = *(const uint32_t*)(q0 + 8*ROW_B + 16);
                const char* q1 = pAl + abase + mi*16*ROW_B + ko;
                al[mi][0] = *(const uint32_t*)(q1);
                al[mi][1] = *(const uint32_t*)(q1 + 8*ROW_B);
                al[mi][2] = *(const uint32_t*)(q1 + 16);
                al[mi][3] = *(const uint32_t*)(q1 + 8*ROW_B + 16);
            }
            #pragma unroll
            for (int ni = 0; ni < 4; ni++) {
                const char* q0 = pBh + bbase + ni*8*ROW_B + ko;
                bh[ni][0] = *(const uint32_t*)(q0);
                bh[ni][1] = *(const uint32_t*)(q0 + 16);
                const char* q1 = pBl + bbase + ni*8*ROW_B + ko;
                bl[ni][0] = *(const uint32_t*)(q1);
                bl[ni][1] = *(const uint32_t*)(q1 + 16);
            }
            #pragma unroll
            for (int mi = 0; mi < 4; mi++)
                #pragma unroll
                for (int ni = 0; ni < 4; ni++) {
                    mma16816(acc[mi][ni], ah[mi][0], ah[mi][1], ah[mi][2], ah[mi][3],
                             bh[ni][0], bh[ni][1]);
                    mma16816(acc[mi][ni], al[mi][0], al[mi][1], al[mi][2], al[mi][3],
                             bh[ni][0], bh[ni][1]);
                    mma16816(acc[mi][ni], ah[mi][0], ah[mi][1], ah[mi][2], ah[mi][3],
                             bl[ni][0], bl[ni][1]);
                }
        }
        __syncthreads();
    }

    // epilogue: registers -> gmem (float2 per half-tile)
    #pragma unroll
    for (int mi = 0; mi < 4; mi++) {
        #pragma unroll
        for (int ni = 0; ni < 4; ni++) {
            int row = bm + wm + mi*16 + gid;
            int col = bn + wn + ni*8 + tig*2;
            float v0 = acc[mi][ni][0]*alpha, v1 = acc[mi][ni][1]*alpha;
            float v2 = acc[mi][ni][2]*alpha, v3 = acc[mi][ni][3]*alpha;
            if (silu) {
                v0 /= (1.f + expf(-v0)); v1 /= (1.f + expf(-v1));
                v2 /= (1.f + expf(-v2)); v3 /= (1.f + expf(-v3));
            }
            *(float2*)&Cb[(long long)row*N + col]       = make_float2(v0, v1);
            *(float2*)&Cb[(long long)(row + 8)*N + col] = make_float2(v2, v3);
        }
    }
}

// ======================= split helpers =======================================
__device__ __forceinline__ void split1(float v, unsigned short& h, unsigned short& l){
    __nv_bfloat16 hb = __float2bfloat16(v);
    __nv_bfloat16 lb = __float2bfloat16(v - __bfloat162float(hb));
    h = __bfloat16_as_ushort(hb); l = __bfloat16_as_ushort(lb);
}

__global__ void downsample_split(const float4* __restrict__ x,
                                 ushort4* __restrict__ xh, ushort4* __restrict__ xl)
{
    int idx = blockIdx.x*blockDim.x + threadIdx.x;
    if (idx >= NB*NR*NC/4) return;
    int c4 = idx & 255, bi = idx >> 8;
    int i = bi & (NR-1), b = bi >> 9;
    long long row = (long long)b*NL + 8*i + 3;
    float4 p = x[row*256 + c4], q = x[(row+1)*256 + c4];
    float v0 = 0.5f*(p.x+q.x), v1 = 0.5f*(p.y+q.y), v2 = 0.5f*(p.z+q.z), v3 = 0.5f*(p.w+q.w);
    ushort4 h, l;
    split1(v0, h.x, l.x); split1(v1, h.y, l.y); split1(v2, h.z, l.z); split1(v3, h.w, l.w);
    xh[idx] = h; xl[idx] = l;
}

__global__ void convert_split(const float4* __restrict__ s,
                              ushort4* __restrict__ h4, ushort4* __restrict__ l4, int n4)
{
    int idx = blockIdx.x*blockDim.x + threadIdx.x;
    if (idx >= n4) return;
    float4 v = s[idx];
    ushort4 h, l;
    split1(v.x, h.x, l.x); split1(v.y, h.y, l.y); split1(v.z, h.z, l.z); split1(v.w, h.w, l.w);
    h4[idx] = h; l4[idx] = l;
}

// rmsnorm(64) + rope(pos = head idx) + split
__global__ void normrope_split(const float* __restrict__ qb, const float* __restrict__ kb,
                               const float* __restrict__ qw, const float* __restrict__ kw,
                               __nv_bfloat16* q1h, __nv_bfloat16* q1l,
                               __nv_bfloat16* q2h, __nv_bfloat16* q2l,
                               __nv_bfloat16* k1h, __nv_bfloat16* k1l,
                               __nv_bfloat16* k2h, __nv_bfloat16* k2l)
{
    int gw   = (blockIdx.x*blockDim.x + threadIdx.x) >> 5;
    int lane = threadIdx.x & 31;
    const int NROWS = NB*NR*NH*2;
    if (gw >= 2*NROWS) return;
    int isK = gw >= NROWS;
    int row = isK ? (gw - NROWS) : gw;
    const float* src = (isK ? kb : qb) + (long long)row * 64;
    float x1 = src[lane], x2 = src[lane+32];
    float ss = x1*x1 + x2*x2;
    #pragma unroll
    for (int o = 16; o; o >>= 1) ss += __shfl_xor_sync(0xffffffffu, ss, o);
    float inv = 1.f / sqrtf(ss*(1.f/64.f) + EPS);
    const float* w = isK ? kw : qw;
    float n1 = x1*inv*w[lane], n2 = x2*inv*w[lane+32];
    int s  = row & 1;
    int h  = (row >> 1) & 7;
    int bi = row >> 4;
    int b  = bi >> 9, i = bi & 511;
    float f = powf(10000.f, -(float)lane * (1.f/32.f));
    float sn, cs; sincosf((float)h * f, &sn, &cs);
    float o1 = n1*cs - n2*sn, o2 = n1*sn + n2*cs;
    __nv_bfloat16 *dh, *dl;
    if (isK) { dh = s ? k2h : k1h; dl = s ? k2l : k1l; }
    else     { dh = s ? q2h : q1h; dl = s ? q2l : q1l; }
    long long off = ((long long)((b*NH + h)*NR) + i) * 64;
    unsigned short hh, ll;
    split1(o1, hh, ll); dh[off+lane]    = __ushort_as_bfloat16(hh); dl[off+lane]    = __ushort_as_bfloat16(ll);
    split1(o2, hh, ll); dh[off+lane+32] = __ushort_as_bfloat16(hh); dl[off+lane+32] = __ushort_as_bfloat16(ll);
}

__global__ void vtrans_split(const float* __restrict__ v,
                             __nv_bfloat16* __restrict__ vth, __nv_bfloat16* __restrict__ vtl)
{
    int idx = blockIdx.x*blockDim.x + threadIdx.x;
    if (idx >= NB*NH*128*NR) return;
    int i = idx & 511, c = (idx >> 9) & 127, bh = idx >> 16;
    int b = bh >> 3, h = bh & 7;
    float vv = v[((long long)(b*NR + i))*NC + h*128 + c];
    unsigned short hh, ll; split1(vv, hh, ll);
    vth[idx] = __ushort_as_bfloat16(hh); vtl[idx] = __ushort_as_bfloat16(ll);
}

__global__ void lambda_kernel(const float* lq1, const float* lk1,
                              const float* lq2, const float* lk2, float* out)
{
    int t = threadIdx.x;
    float a = lq1[t]*lk1[t] + lq1[t+32]*lk1[t+32];
    float b = lq2[t]*lk2[t] + lq2[t+32]*lk2[t+32];
    #pragma unroll
    for (int o = 16; o; o >>= 1) {
        a += __shfl_xor_sync(0xffffffffu, a, o);
        b += __shfl_xor_sync(0xffffffffu, b, o);
    }
    if (t == 0) out[0] = expf(a) - expf(b) + LAMBDA_INIT;
}

// dual softmax + combine -> split bf16 probs
__global__ void softmax_combine(const float* __restrict__ s1, const float* __restrict__ s2,
                                const float* __restrict__ lamp,
                                ushort4* __restrict__ ph, ushort4* __restrict__ pl)
{
    int gw   = (blockIdx.x*blockDim.x + threadIdx.x) >> 5;
    int lane = threadIdx.x & 31;
    if (gw >= NB*NH*NR) return;
    const float4* r1 = (const float4*)(s1 + (long long)gw * NR);
    const float4* r2 = (const float4*)(s2 + (long long)gw * NR);
    float4 v1[4], v2[4];
    float m1 = -1e30f, m2 = -1e30f;
    #pragma unroll
    for (int i = 0; i < 4; i++) {
        v1[i] = r1[lane + 32*i]; v2[i] = r2[lane + 32*i];
        m1 = fmaxf(m1, fmaxf(fmaxf(v1[i].x, v1[i].y), fmaxf(v1[i].z, v1[i].w)));
        m2 = fmaxf(m2, fmaxf(fmaxf(v2[i].x, v2[i].y), fmaxf(v2[i].z, v2[i].w)));
    }
    #pragma unroll
    for (int o = 16; o; o >>= 1) {
        m1 = fmaxf(m1, __shfl_xor_sync(0xffffffffu, m1, o));
        m2 = fmaxf(m2, __shfl_xor_sync(0xffffffffu, m2, o));
    }
    float a1 = 0.f, a2 = 0.f;
    #pragma unroll
    for (int i = 0; i < 4; i++) {
        v1[i].x = expf(v1[i].x-m1); v1[i].y = expf(v1[i].y-m1);
        v1[i].z = expf(v1[i].z-m1); v1[i].w = expf(v1[i].w-m1);
        v2[i].x = expf(v2[i].x-m2); v2[i].y = expf(v2[i].y-m2);
        v2[i].z = expf(v2[i].z-m2); v2[i].w = expf(v2[i].w-m2);
        a1 += v1[i].x+v1[i].y+v1[i].z+v1[i].w;
        a2 += v2[i].x+v2[i].y+v2[i].z+v2[i].w;
    }
    #pragma unroll
    for (int o = 16; o; o >>= 1) {
        a1 += __shfl_xor_sync(0xffffffffu, a1, o);
        a2 += __shfl_xor_sync(0xffffffffu, a2, o);
    }
    float is1 = 1.f/a1, is2 = lamp[0]/a2;
    #pragma unroll
    for (int i = 0; i < 4; i++) {
        float o0 = v1[i].x*is1 - v2[i].x*is2;
        float o1 = v1[i].y*is1 - v2[i].y*is2;
        float o2 = v1[i].z*is1 - v2[i].z*is2;
        float o3 = v1[i].w*is1 - v2[i].w*is2;
        ushort4 h, l;
        split1(o0,h.x,l.x); split1(o1,h.y,l.y); split1(o2,h.z,l.z); split1(o3,h.w,l.w);
        ph[(long long)gw*128 + lane + 32*i] = h;
        pl[(long long)gw*128 + lane + 32*i] = l;
    }
}

// head rmsnorm(128) * (1-lambda_init) -> (B,r,C) layout, split bf16
__global__ void headnorm_split(const float* __restrict__ diff, const float* __restrict__ hw,
                               ushort4* __restrict__ yh, ushort4* __restrict__ yl)
{
    int gw   = (blockIdx.x*blockDim.x + threadIdx.x) >> 5;
    int lane = threadIdx.x & 31;
    if (gw >= NB*NH*NR) return;
    const float4* src = (const float4*)(diff + (long long)gw * 128);
    float4 a = src[lane];
    float ss = a.x*a.x + a.y*a.y + a.z*a.z + a.w*a.w;
    #pragma unroll
    for (int o = 16; o; o >>= 1) ss += __shfl_xor_sync(0xffffffffu, ss, o);
    float inv = (1.f - LAMBDA_INIT) / sqrtf(ss*(1.f/128.f) + EPS);
    int bh = gw >> 9, i = gw & 511;
    int b = bh >> 3, h = bh & 7;
    float4 w = ((const float4*)hw)[lane];
    float o0 = a.x*inv*w.x, o1 = a.y*inv*w.y, o2 = a.z*inv*w.z, o3 = a.w*inv*w.w;
    ushort4 hh, ll;
    split1(o0,hh.x,ll.x); split1(o1,hh.y,ll.y); split1(o2,hh.z,ll.z); split1(o3,hh.w,ll.w);
    long long oidx = (long long)(b*NR + i)*256 + h*32 + lane;
    yh[oidx] = hh; yl[oidx] = ll;
}

// upsample 512 -> 4096
__global__ void upsample_kernel(const float4* __restrict__ lr, float4* __restrict__ out)
{
    int idx = blockIdx.x*blockDim.x + threadIdx.x;
    if (idx >= NB*NL*NC/4) return;
    int c4 = idx & 255, j = (idx >> 8) & (NL-1), b = idx >> 20;
    float coords = fminf(fmaxf(((float)j + 0.5f)*0.125f - 0.5f, 0.f), 511.f);
    int lo = (int)coords;
    int hi = min(lo + 1, 511);
    float w = coords - (float)lo, w0 = 1.f - w;
    long long base = (long long)b * NR * 256;
    float4 a = lr[base + (long long)lo*256 + c4];
    float4 c = lr[base + (long long)hi*256 + c4];
    float4 o;
    o.x = a.x*w0 + c.x*w; o.y = a.y*w0 + c.y*w;
    o.z = a.z*w0 + c.z*w; o.w = a.w*w0 + c.w*w;
    out[idx] = o;
}

// ======================= host launcher =======================================
extern "C" void kernel_launch(void* const* d_in, const int* in_sizes, int n_in,
                              void* d_out, int out_size)
{
    const float* x   = (const float*)d_in[0];
    const float* Wq  = (const float*)d_in[1];
    const float* Wk  = (const float*)d_in[2];
    const float* Wv  = (const float*)d_in[3];
    const float* Wo  = (const float*)d_in[4];
    const float* qw  = (const float*)d_in[5];
    const float* kw  = (const float*)d_in[6];
    const float* hw  = (const float*)d_in[7];
    const float* lq1 = (const float*)d_in[8];
    const float* lk1 = (const float*)d_in[9];
    const float* lq2 = (const float*)d_in[10];
    const float* lk2 = (const float*)d_in[11];

    float* full_out = (float*)d_out;
    float* lowrank  = full_out + (size_t)NB*NL*NC;

    #define GS(p, s) cudaGetSymbolAddress((void**)&p, s)
    __nv_bfloat16 *xdh,*xdl,*Wqh,*Wql,*Wkh,*Wkl,*Wvh,*Wvl,*Woh,*Wol;
    __nv_bfloat16 *q1h,*q1l,*q2h,*q2l,*k1h,*k1l,*k2h,*k2l,*vth,*vtl,*ph,*pl,*yh,*yl;
    float *q,*k,*v,*s1,*s2,*diff,*lam;
    GS(xdh,g_xdh); GS(xdl,g_xdl);
    GS(Wqh,g_Wqh); GS(Wql,g_Wql); GS(Wkh,g_Wkh); GS(Wkl,g_Wkl);
    GS(Wvh,g_Wvh); GS(Wvl,g_Wvl); GS(Woh,g_Woh); GS(Wol,g_Wol);
    GS(q,g_q); GS(k,g_k); GS(v,g_v);
    GS(q1h,g_q1h); GS(q1l,g_q1l); GS(q2h,g_q2h); GS(q2l,g_q2l);
    GS(k1h,g_k1h); GS(k1l,g_k1l); GS(k2h,g_k2h); GS(k2l,g_k2l);
    GS(vth,g_vth); GS(vtl,g_vtl);
    GS(s1,g_s1); GS(s2,g_s2); GS(ph,g_ph); GS(pl,g_pl);
    GS(diff,g_diff); GS(yh,g_yh); GS(yl,g_yl); GS(lam,g_lam);
    #undef GS

    cudaFuncSetAttribute(gemm_mma, cudaFuncAttributeMaxDynamicSharedMemorySize, GEMM_SMEM);

    // 1. downsample + split, weight splits
    downsample_split<<<(NB*NR*NC/4 + 255)/256, 256>>>((const float4*)x, (ushort4*)xdh, (ushort4*)xdl);
    int wn4 = NC*NC/4;
    convert_split<<<(wn4+255)/256, 256>>>((const float4*)Wq, (ushort4*)Wqh, (ushort4*)Wql, wn4);
    convert_split<<<(wn4+255)/256, 256>>>((const float4*)Wk, (ushort4*)Wkh, (ushort4*)Wkl, wn4);
    convert_split<<<(wn4+255)/256, 256>>>((const float4*)Wv, (ushort4*)Wvh, (ushort4*)Wvl, wn4);
    convert_split<<<(wn4+255)/256, 256>>>((const float4*)Wo, (ushort4*)Woh, (ushort4*)Wol, wn4);

    // 2. QKV projections: M=2048, N=1024, K=1024
    dim3 gqkv(NC/128, (NB*NR)/128, 1);
    gemm_mma<<<gqkv, 256, GEMM_SMEM>>>(xdh, xdl, Wqh, Wql, q, NB*NR, NC, NC, 0,0,0, 1.f, 0);
    gemm_mma<<<gqkv, 256, GEMM_SMEM>>>(xdh, xdl, Wkh, Wkl, k, NB*NR, NC, NC, 0,0,0, 1.f, 0);
    gemm_mma<<<gqkv, 256, GEMM_SMEM>>>(xdh, xdl, Wvh, Wvl, v, NB*NR, NC, NC, 0,0,0, 1.f, 0);

    // 3. norm+rope+split, v transpose+split, lambda
    normrope_split<<<(2*NB*NR*NH*2*32 + 255)/256, 256>>>(q, k, qw, kw,
        q1h,q1l,q2h,q2l,k1h,k1l,k2h,k2l);
    vtrans_split<<<(NB*NH*128*NR + 255)/256, 256>>>(v, vth, vtl);
    lambda_kernel<<<1, 32>>>(lq1, lk1, lq2, lk2, lam);

    // 4. attention scores (batched, alpha = d^-0.5)
    dim3 gsc(NR/128, NR/128, NB*NH);
    gemm_mma<<<gsc, 256, GEMM_SMEM>>>(q1h, q1l, k1h, k1l, s1, NR, NR, ND,
        (long long)NR*ND, (long long)NR*ND, (long long)NR*NR, 0.125f, 0);
    gemm_mma<<<gsc, 256, GEMM_SMEM>>>(q2h, q2l, k2h, k2l, s2, NR, NR, ND,
        (long long)NR*ND, (long long)NR*ND, (long long)NR*NR, 0.125f, 0);

    // 5. dual softmax + combine -> split probs
    softmax_combine<<<(NB*NH*NR*32 + 255)/256, 256>>>(s1, s2, lam, (ushort4*)ph, (ushort4*)pl);

    // 6. PV: diff = p @ v (batched M=512, N=128, K=512)
    dim3 gpv(1, NR/128, NB*NH);
    gemm_mma<<<gpv, 256, GEMM_SMEM>>>(ph, pl, vth, vtl, diff, NR, 128, NR,
        (long long)NR*NR, (long long)128*NR, (long long)NR*128, 1.f, 0);

    // 7. head rmsnorm * (1-lambda) -> split y
    headnorm_split<<<(NB*NH*NR*32 + 255)/256, 256>>>(diff, hw, (ushort4*)yh, (ushort4*)yl);

    // 8. Wo projection + fused silu -> lowrank_out
    gemm_mma<<<gqkv, 256, GEMM_SMEM>>>(yh, yl, Woh, Wol, lowrank, NB*NR, NC, NC, 0,0,0, 1.f, 1);

    // 9. upsample -> full_out
    upsample_kernel<<<(NB*NL*NC/4 + 255)/256, 256>>>((const float4*)lowrank, (float4*)full_out);
}

// round 4
// speedup vs baseline: 2.2591x; 1.0266x over previous
#include <cuda_runtime.h>
#include <cuda_bf16.h>
#include <math.h>
#include <stdint.h>

#define NB 4
#define NL 4096
#define NC 1024
#define NH 8
#define NR 512
#define ND 64
#define LAMBDA_INIT 0.8f
#define EPS 1e-6f

// ======================= device scratch (no allocs allowed) ==================
__device__ __nv_bfloat16 g_xdh[NB*NR*NC], g_xdl[NB*NR*NC];
__device__ __nv_bfloat16 g_Wqh[NC*NC], g_Wql[NC*NC];
__device__ __nv_bfloat16 g_Wkh[NC*NC], g_Wkl[NC*NC];
__device__ __nv_bfloat16 g_Wvh[NC*NC], g_Wvl[NC*NC];
__device__ __nv_bfloat16 g_Woh[NC*NC], g_Wol[NC*NC];
__device__ float g_q[NB*NR*NC], g_k[NB*NR*NC], g_v[NB*NR*NC];
__device__ __nv_bfloat16 g_q1h[NB*NH*NR*ND], g_q1l[NB*NH*NR*ND];
__device__ __nv_bfloat16 g_q2h[NB*NH*NR*ND], g_q2l[NB*NH*NR*ND];
__device__ __nv_bfloat16 g_k1h[NB*NH*NR*ND], g_k1l[NB*NH*NR*ND];
__device__ __nv_bfloat16 g_k2h[NB*NH*NR*ND], g_k2l[NB*NH*NR*ND];
__device__ __nv_bfloat16 g_vth[NB*NH*128*NR], g_vtl[NB*NH*128*NR];
__device__ float g_s1[NB*NH*NR*NR], g_s2[NB*NH*NR*NR];
__device__ __nv_bfloat16 g_ph[NB*NH*NR*NR], g_pl[NB*NH*NR*NR];
__device__ float g_diff[NB*NH*NR*128];
__device__ __nv_bfloat16 g_yh[NB*NR*NC], g_yl[NB*NR*NC];
__device__ float g_lam[1];

// ======================= asm helpers (all sm_80-portable) ====================
__device__ __forceinline__ uint32_t smem_u32(const void* p){
    uint32_t a;
    asm("{ .reg .u64 t; cvta.to.shared.u64 t, %1; cvt.u32.u64 %0, t; }" : "=r"(a) : "l"(p));
    return a;
}
__device__ __forceinline__ void cpa16(uint32_t d, const void* s){
    asm volatile("cp.async.cg.shared.global [%0], [%1], 16;" :: "r"(d), "l"(s));
}
#define CP_COMMIT() asm volatile("cp.async.commit_group;" ::: "memory")
#define CP_WAIT0()  asm volatile("cp.async.wait_group 0;" ::: "memory")
#define CP_WAIT1()  asm volatile("cp.async.wait_group 1;" ::: "memory")

__device__ __forceinline__ void mma16816(float* c,
    uint32_t a0, uint32_t a1, uint32_t a2, uint32_t a3, uint32_t b0, uint32_t b1)
{
    asm volatile(
        "mma.sync.aligned.m16n8k16.row.col.f32.bf16.bf16.f32 "
        "{%0,%1,%2,%3}, {%4,%5,%6,%7}, {%8,%9}, {%0,%1,%2,%3};"
        : "+f"(c[0]), "+f"(c[1]), "+f"(c[2]), "+f"(c[3])
        : "r"(a0), "r"(a1), "r"(a2), "r"(a3), "r"(b0), "r"(b1));
}
#define LDSM4(r0,r1,r2,r3, addr) \
    asm volatile("ldmatrix.sync.aligned.m8n8.x4.shared.b16 {%0,%1,%2,%3}, [%4];" \
        : "=r"(r0),"=r"(r1),"=r"(r2),"=r"(r3) : "r"(addr))

// ======================= HMMA split-bf16 batched NT GEMM =====================
// C[m,n] = alpha * sum_k (Ah+Al)[m,k]*(Bh+Bl)[n,k]   (Al*Bl dropped)
// CTA 128x128, BK=32, 8 warps (2x4), warp tile 64x32, 3-stage cp.async.
// smem rows padded to 80B -> ldmatrix 8-row phases hit all 32 banks.
#define ROW_B   80
#define TILE_B  (128*ROW_B)          // 10240
#define STG_B   (4*TILE_B)           // Ah,Al,Bh,Bl = 40960
#define GEMM_SMEM (3*STG_B)          // 122880

__device__ __forceinline__ void ld_stage(uint32_t sbase, int tid, long long c32,
    const __nv_bfloat16* Ahb, const __nv_bfloat16* Alb,
    const __nv_bfloat16* Bhb, const __nv_bfloat16* Blb, int K)
{
    int seg = tid & 3;
    #pragma unroll
    for (int it = 0; it < 8; it++) {
        int i = tid + it*256;
        int r = (i >> 2) & 127;
        const __nv_bfloat16* src =
            (it < 2) ? Ahb : (it < 4) ? Alb : (it < 6) ? Bhb : Blb;
        cpa16(sbase + (it >> 1)*TILE_B + r*ROW_B + seg*16,
              src + (long long)r*K + c32 + seg*8);
    }
    CP_COMMIT();
}

__global__ __launch_bounds__(256, 1)
void gemm_mma(const __nv_bfloat16* __restrict__ Ah, const __nv_bfloat16* __restrict__ Al,
              const __nv_bfloat16* __restrict__ Bh, const __nv_bfloat16* __restrict__ Bl,
              float* __restrict__ C, int M, int N, int K,
              long long sA, long long sB, long long sC, float alpha, int silu)
{
    extern __shared__ char sm[];
    uint32_t sb = smem_u32(sm);
    const int tid  = threadIdx.x;
    const int wid  = tid >> 5, lane = tid & 31;
    const int gid  = lane >> 2, tig = lane & 3;
    const int wm   = (wid & 1) * 64;       // warp row offset
    const int wn   = (wid >> 1) * 32;      // warp col offset
    const int bm   = blockIdx.y * 128, bn = blockIdx.x * 128;

    const __nv_bfloat16* Ahb = Ah + blockIdx.z*sA + (long long)bm*K;
    const __nv_bfloat16* Alb = Al + blockIdx.z*sA + (long long)bm*K;
    const __nv_bfloat16* Bhb = Bh + blockIdx.z*sB + (long long)bn*K;
    const __nv_bfloat16* Blb = Bl + blockIdx.z*sB + (long long)bn*K;
    float* Cb = C + blockIdx.z*sC;

    // ldmatrix lane->address mapping
    // A (x4: m0 rows0-7 k0-15lo, m1 rows8-15 lo, m2 rows0-7 hi, m3 rows8-15 hi)
    const int a_row = (lane & 7) + ((lane & 8)  ? 8 : 0);
    const int a_col = (lane & 16) ? 16 : 0;
    // B (x4: m0 n0-7 klo, m1 n0-7 khi, m2 n8-15 klo, m3 n8-15 khi)
    const int b_row = (lane & 7) + ((lane & 16) ? 8 : 0);
    const int b_col = (lane & 8)  ? 16 : 0;

    float acc[4][4][4];
    #pragma unroll
    for (int mi = 0; mi < 4; mi++)
        #pragma unroll
        for (int ni = 0; ni < 4; ni++)
            #pragma unroll
            for (int t = 0; t < 4; t++) acc[mi][ni][t] = 0.f;

    const int nch = K >> 5;
    ld_stage(sb, tid, 0, Ahb, Alb, Bhb, Blb, K);
    if (nch > 1) ld_stage(sb + STG_B, tid, 32, Ahb, Alb, Bhb, Blb, K);

    for (int c = 0; c < nch; c++) {
        if (c + 1 < nch) CP_WAIT1(); else CP_WAIT0();
        __syncthreads();
        if (c + 2 < nch)
            ld_stage(sb + ((c + 2) % 3)*STG_B, tid, (long long)(c + 2)*32,
                     Ahb, Alb, Bhb, Blb, K);

        const uint32_t p = sb + (c % 3)*STG_B;
        const uint32_t pAh = p,            pAl = p +   TILE_B;
        const uint32_t pBh = p + 2*TILE_B, pBl = p + 3*TILE_B;

        #pragma unroll
        for (int kk = 0; kk < 2; kk++) {
            const int ko = kk*32;
            uint32_t ah[4][4], al[4][4], bh[4][2], bl[4][2];
            #pragma unroll
            for (int mi = 0; mi < 4; mi++) {
                uint32_t ad = pAh + (wm + mi*16 + a_row)*ROW_B + ko + a_col;
                LDSM4(ah[mi][0], ah[mi][1], ah[mi][2], ah[mi][3], ad);
                uint32_t ad2 = pAl + (wm + mi*16 + a_row)*ROW_B + ko + a_col;
                LDSM4(al[mi][0], al[mi][1], al[mi][2], al[mi][3], ad2);
            }
            #pragma unroll
            for (int nj = 0; nj < 2; nj++) {
                uint32_t bd = pBh + (wn + nj*16 + b_row)*ROW_B + ko + b_col;
                LDSM4(bh[2*nj][0], bh[2*nj][1], bh[2*nj+1][0], bh[2*nj+1][1], bd);
                uint32_t bd2 = pBl + (wn + nj*16 + b_row)*ROW_B + ko + b_col;
                LDSM4(bl[2*nj][0], bl[2*nj][1], bl[2*nj+1][0], bl[2*nj+1][1], bd2);
            }
            #pragma unroll
            for (int mi = 0; mi < 4; mi++)
                #pragma unroll
                for (int ni = 0; ni < 4; ni++) {
                    mma16816(acc[mi][ni], ah[mi][0], ah[mi][1], ah[mi][2], ah[mi][3],
                             bh[ni][0], bh[ni][1]);
                    mma16816(acc[mi][ni], al[mi][0], al[mi][1], al[mi][2], al[mi][3],
                             bh[ni][0], bh[ni][1]);
                    mma16816(acc[mi][ni], ah[mi][0], ah[mi][1], ah[mi][2], ah[mi][3],
                             bl[ni][0], bl[ni][1]);
                }
        }
        __syncthreads();
    }

    // epilogue
    #pragma unroll
    for (int mi = 0; mi < 4; mi++) {
        #pragma unroll
        for (int ni = 0; ni < 4; ni++) {
            int row = bm + wm + mi*16 + gid;
            int col = bn + wn + ni*8 + tig*2;
            float v0 = acc[mi][ni][0]*alpha, v1 = acc[mi][ni][1]*alpha;
            float v2 = acc[mi][ni][2]*alpha, v3 = acc[mi][ni][3]*alpha;
            if (silu) {
                v0 /= (1.f + expf(-v0)); v1 /= (1.f + expf(-v1));
                v2 /= (1.f + expf(-v2)); v3 /= (1.f + expf(-v3));
            }
            *(float2*)&Cb[(long long)row*N + col]       = make_float2(v0, v1);
            *(float2*)&Cb[(long long)(row + 8)*N + col] = make_float2(v2, v3);
        }
    }
}

// ======================= split helpers =======================================
__device__ __forceinline__ void split1(float v, unsigned short& h, unsigned short& l){
    __nv_bfloat16 hb = __float2bfloat16(v);
    __nv_bfloat16 lb = __float2bfloat16(v - __bfloat162float(hb));
    h = __bfloat16_as_ushort(hb); l = __bfloat16_as_ushort(lb);
}

__global__ void downsample_split(const float4* __restrict__ x,
                                 ushort4* __restrict__ xh, ushort4* __restrict__ xl)
{
    int idx = blockIdx.x*blockDim.x + threadIdx.x;
    if (idx >= NB*NR*NC/4) return;
    int c4 = idx & 255, bi = idx >> 8;
    int i = bi & (NR-1), b = bi >> 9;
    long long row = (long long)b*NL + 8*i + 3;
    float4 p = x[row*256 + c4], q = x[(row+1)*256 + c4];
    float v0 = 0.5f*(p.x+q.x), v1 = 0.5f*(p.y+q.y), v2 = 0.5f*(p.z+q.z), v3 = 0.5f*(p.w+q.w);
    ushort4 h, l;
    split1(v0, h.x, l.x); split1(v1, h.y, l.y); split1(v2, h.z, l.z); split1(v3, h.w, l.w);
    xh[idx] = h; xl[idx] = l;
}

// all 4 weight matrices in one launch (blockIdx.y selects)
__global__ void convert_split4(const float4* __restrict__ Wq, const float4* __restrict__ Wk,
                               const float4* __restrict__ Wv, const float4* __restrict__ Wo,
                               ushort4* qh, ushort4* ql, ushort4* kh, ushort4* kl,
                               ushort4* vh, ushort4* vl, ushort4* oh, ushort4* ol)
{
    int idx = blockIdx.x*blockDim.x + threadIdx.x;
    if (idx >= NC*NC/4) return;
    const float4* s; ushort4 *dh, *dl;
    switch (blockIdx.y) {
        case 0: s = Wq; dh = qh; dl = ql; break;
        case 1: s = Wk; dh = kh; dl = kl; break;
        case 2: s = Wv; dh = vh; dl = vl; break;
        default:s = Wo; dh = oh; dl = ol; break;
    }
    float4 v = s[idx];
    ushort4 h, l;
    split1(v.x, h.x, l.x); split1(v.y, h.y, l.y); split1(v.z, h.z, l.z); split1(v.w, h.w, l.w);
    dh[idx] = h; dl[idx] = l;
}

// rmsnorm(64) + rope(pos = head idx) + split
__global__ void normrope_split(const float* __restrict__ qb, const float* __restrict__ kb,
                               const float* __restrict__ qw, const float* __restrict__ kw,
                               __nv_bfloat16* q1h, __nv_bfloat16* q1l,
                               __nv_bfloat16* q2h, __nv_bfloat16* q2l,
                               __nv_bfloat16* k1h, __nv_bfloat16* k1l,
                               __nv_bfloat16* k2h, __nv_bfloat16* k2l)
{
    int gw   = (blockIdx.x*blockDim.x + threadIdx.x) >> 5;
    int lane = threadIdx.x & 31;
    const int NROWS = NB*NR*NH*2;
    if (gw >= 2*NROWS) return;
    int isK = gw >= NROWS;
    int row = isK ? (gw - NROWS) : gw;
    const float* src = (isK ? kb : qb) + (long long)row * 64;
    float x1 = src[lane], x2 = src[lane+32];
    float ss = x1*x1 + x2*x2;
    #pragma unroll
    for (int o = 16; o; o >>= 1) ss += __shfl_xor_sync(0xffffffffu, ss, o);
    float inv = 1.f / sqrtf(ss*(1.f/64.f) + EPS);
    const float* w = isK ? kw : qw;
    float n1 = x1*inv*w[lane], n2 = x2*inv*w[lane+32];
    int s  = row & 1;
    int h  = (row >> 1) & 7;
    int bi = row >> 4;
    int b  = bi >> 9, i = bi & 511;
    float f = powf(10000.f, -(float)lane * (1.f/32.f));
    float sn, cs; sincosf((float)h * f, &sn, &cs);
    float o1 = n1*cs - n2*sn, o2 = n1*sn + n2*cs;
    __nv_bfloat16 *dh, *dl;
    if (isK) { dh = s ? k2h : k1h; dl = s ? k2l : k1l; }
    else     { dh = s ? q2h : q1h; dl = s ? q2l : q1l; }
    long long off = ((long long)((b*NH + h)*NR) + i) * 64;
    unsigned short hh, ll;
    split1(o1, hh, ll); dh[off+lane]    = __ushort_as_bfloat16(hh); dl[off+lane]    = __ushort_as_bfloat16(ll);
    split1(o2, hh, ll); dh[off+lane+32] = __ushort_as_bfloat16(hh); dl[off+lane+32] = __ushort_as_bfloat16(ll);
}

__global__ void vtrans_split(const float* __restrict__ v,
                             __nv_bfloat16* __restrict__ vth, __nv_bfloat16* __restrict__ vtl)
{
    int idx = blockIdx.x*blockDim.x + threadIdx.x;
    if (idx >= NB*NH*128*NR) return;
    int i = idx & 511, c = (idx >> 9) & 127, bh = idx >> 16;
    int b = bh >> 3, h = bh & 7;
    float vv = v[((long long)(b*NR + i))*NC + h*128 + c];
    unsigned short hh, ll; split1(vv, hh, ll);
    vth[idx] = __ushort_as_bfloat16(hh); vtl[idx] = __ushort_as_bfloat16(ll);
}

__global__ void lambda_kernel(const float* lq1, const float* lk1,
                              const float* lq2, const float* lk2, float* out)
{
    int t = threadIdx.x;
    float a = lq1[t]*lk1[t] + lq1[t+32]*lk1[t+32];
    float b = lq2[t]*lk2[t] + lq2[t+32]*lk2[t+32];
    #pragma unroll
    for (int o = 16; o; o >>= 1) {
        a += __shfl_xor_sync(0xffffffffu, a, o);
        b += __shfl_xor_sync(0xffffffffu, b, o);
    }
    if (t == 0) out[0] = expf(a) - expf(b) + LAMBDA_INIT;
}

// dual softmax + combine -> split bf16 probs
__global__ void softmax_combine(const float* __restrict__ s1, const float* __restrict__ s2,
                                const float* __restrict__ lamp,
                                ushort4* __restrict__ ph, ushort4* __restrict__ pl)
{
    int gw   = (blockIdx.x*blockDim.x + threadIdx.x) >> 5;
    int lane = threadIdx.x & 31;
    if (gw >= NB*NH*NR) return;
    const float4* r1 = (const float4*)(s1 + (long long)gw * NR);
    const float4* r2 = (const float4*)(s2 + (long long)gw * NR);
    float4 v1[4], v2[4];
    float m1 = -1e30f, m2 = -1e30f;
    #pragma unroll
    for (int i = 0; i < 4; i++) {
        v1[i] = r1[lane + 32*i]; v2[i] = r2[lane + 32*i];
        m1 = fmaxf(m1, fmaxf(fmaxf(v1[i].x, v1[i].y), fmaxf(v1[i].z, v1[i].w)));
        m2 = fmaxf(m2, fmaxf(fmaxf(v2[i].x, v2[i].y), fmaxf(v2[i].z, v2[i].w)));
    }
    #pragma unroll
    for (int o = 16; o; o >>= 1) {
        m1 = fmaxf(m1, __shfl_xor_sync(0xffffffffu, m1, o));
        m2 = fmaxf(m2, __shfl_xor_sync(0xffffffffu, m2, o));
    }
    float a1 = 0.f, a2 = 0.f;
    #pragma unroll
    for (int i = 0; i < 4; i++) {
        v1[i].x = expf(v1[i].x-m1); v1[i].y = expf(v1[i].y-m1);
        v1[i].z = expf(v1[i].z-m1); v1[i].w = expf(v1[i].w-m1);
        v2[i].x = expf(v2[i].x-m2); v2[i].y = expf(v2[i].y-m2);
        v2[i].z = expf(v2[i].z-m2); v2[i].w = expf(v2[i].w-m2);
        a1 += v1[i].x+v1[i].y+v1[i].z+v1[i].w;
        a2 += v2[i].x+v2[i].y+v2[i].z+v2[i].w;
    }
    #pragma unroll
    for (int o = 16; o; o >>= 1) {
        a1 += __shfl_xor_sync(0xffffffffu, a1, o);
        a2 += __shfl_xor_sync(0xffffffffu, a2, o);
    }
    float is1 = 1.f/a1, is2 = lamp[0]/a2;
    #pragma unroll
    for (int i = 0; i < 4; i++) {
        float o0 = v1[i].x*is1 - v2[i].x*is2;
        float o1 = v1[i].y*is1 - v2[i].y*is2;
        float o2 = v1[i].z*is1 - v2[i].z*is2;
        float o3 = v1[i].w*is1 - v2[i].w*is2;
        ushort4 h, l;
        split1(o0,h.x,l.x); split1(o1,h.y,l.y); split1(o2,h.z,l.z); split1(o3,h.w,l.w);
        ph[(long long)gw*128 + lane + 32*i] = h;
        pl[(long long)gw*128 + lane + 32*i] = l;
    }
}

// head rmsnorm(128) * (1-lambda_init) -> (B,r,C) layout, split bf16
__global__ void headnorm_split(const float* __restrict__ diff, const float* __restrict__ hw,
                               ushort4* __restrict__ yh, ushort4* __restrict__ yl)
{
    int gw   = (blockIdx.x*blockDim.x + threadIdx.x) >> 5;
    int lane = threadIdx.x & 31;
    if (gw >= NB*NH*NR) return;
    const float4* src = (const float4*)(diff + (long long)gw * 128);
    float4 a = src[lane];
    float ss = a.x*a.x + a.y*a.y + a.z*a.z + a.w*a.w;
    #pragma unroll
    for (int o = 16; o; o >>= 1) ss += __shfl_xor_sync(0xffffffffu, ss, o);
    float inv = (1.f - LAMBDA_INIT) / sqrtf(ss*(1.f/128.f) + EPS);
    int bh = gw >> 9, i = gw & 511;
    int b = bh >> 3, h = bh & 7;
    float4 w = ((const float4*)hw)[lane];
    float o0 = a.x*inv*w.x, o1 = a.y*inv*w.y, o2 = a.z*inv*w.z, o3 = a.w*inv*w.w;
    ushort4 hh, ll;
    split1(o0,hh.x,ll.x); split1(o1,hh.y,ll.y); split1(o2,hh.z,ll.z); split1(o3,hh.w,ll.w);
    long long oidx = (long long)(b*NR + i)*256 + h*32 + lane;
    yh[oidx] = hh; yl[oidx] = ll;
}

// upsample 512 -> 4096
__global__ void upsample_kernel(const float4* __restrict__ lr, float4* __restrict__ out)
{
    int idx = blockIdx.x*blockDim.x + threadIdx.x;
    if (idx >= NB*NL*NC/4) return;
    int c4 = idx & 255, j = (idx >> 8) & (NL-1), b = idx >> 20;
    float coords = fminf(fmaxf(((float)j + 0.5f)*0.125f - 0.5f, 0.f), 511.f);
    int lo = (int)coords;
    int hi = min(lo + 1, 511);
    float w = coords - (float)lo, w0 = 1.f - w;
    long long base = (long long)b * NR * 256;
    float4 a = lr[base + (long long)lo*256 + c4];
    float4 c = lr[base + (long long)hi*256 + c4];
    float4 o;
    o.x = a.x*w0 + c.x*w; o.y = a.y*w0 + c.y*w;
    o.z = a.z*w0 + c.z*w; o.w = a.w*w0 + c.w*w;
    out[idx] = o;
}

// ======================= host launcher =======================================
extern "C" void kernel_launch(void* const* d_in, const int* in_sizes, int n_in,
                              void* d_out, int out_size)
{
    const float* x   = (const float*)d_in[0];
    const float* Wq  = (const float*)d_in[1];
    const float* Wk  = (const float*)d_in[2];
    const float* Wv  = (const float*)d_in[3];
    const float* Wo  = (const float*)d_in[4];
    const float* qw  = (const float*)d_in[5];
    const float* kw  = (const float*)d_in[6];
    const float* hw  = (const float*)d_in[7];
    const float* lq1 = (const float*)d_in[8];
    const float* lk1 = (const float*)d_in[9];
    const float* lq2 = (const float*)d_in[10];
    const float* lk2 = (const float*)d_in[11];

    float* full_out = (float*)d_out;
    float* lowrank  = full_out + (size_t)NB*NL*NC;

    #define GS(p, s) cudaGetSymbolAddress((void**)&p, s)
    __nv_bfloat16 *xdh,*xdl,*Wqh,*Wql,*Wkh,*Wkl,*Wvh,*Wvl,*Woh,*Wol;
    __nv_bfloat16 *q1h,*q1l,*q2h,*q2l,*k1h,*k1l,*k2h,*k2l,*vth,*vtl,*ph,*pl,*yh,*yl;
    float *q,*k,*v,*s1,*s2,*diff,*lam;
    GS(xdh,g_xdh); GS(xdl,g_xdl);
    GS(Wqh,g_Wqh); GS(Wql,g_Wql); GS(Wkh,g_Wkh); GS(Wkl,g_Wkl);
    GS(Wvh,g_Wvh); GS(Wvl,g_Wvl); GS(Woh,g_Woh); GS(Wol,g_Wol);
    GS(q,g_q); GS(k,g_k); GS(v,g_v);
    GS(q1h,g_q1h); GS(q1l,g_q1l); GS(q2h,g_q2h); GS(q2l,g_q2l);
    GS(k1h,g_k1h); GS(k1l,g_k1l); GS(k2h,g_k2h); GS(k2l,g_k2l);
    GS(vth,g_vth); GS(vtl,g_vtl);
    GS(s1,g_s1); GS(s2,g_s2); GS(ph,g_ph); GS(pl,g_pl);
    GS(diff,g_diff); GS(yh,g_yh); GS(yl,g_yl); GS(lam,g_lam);
    #undef GS

    cudaFuncSetAttribute(gemm_mma, cudaFuncAttributeMaxDynamicSharedMemorySize, GEMM_SMEM);

    // 1. downsample + split; weights split (one fused launch)
    downsample_split<<<(NB*NR*NC/4 + 255)/256, 256>>>((const float4*)x, (ushort4*)xdh, (ushort4*)xdl);
    dim3 gcv((NC*NC/4 + 255)/256, 4);
    convert_split4<<<gcv, 256>>>((const float4*)Wq, (const float4*)Wk,
                                 (const float4*)Wv, (const float4*)Wo,
                                 (ushort4*)Wqh, (ushort4*)Wql, (ushort4*)Wkh, (ushort4*)Wkl,
                                 (ushort4*)Wvh, (ushort4*)Wvl, (ushort4*)Woh, (ushort4*)Wol);

    // 2. QKV projections: M=2048, N=1024, K=1024
    dim3 gqkv(NC/128, (NB*NR)/128, 1);
    gemm_mma<<<gqkv, 256, GEMM_SMEM>>>(xdh, xdl, Wqh, Wql, q, NB*NR, NC, NC, 0,0,0, 1.f, 0);
    gemm_mma<<<gqkv, 256, GEMM_SMEM>>>(xdh, xdl, Wkh, Wkl, k, NB*NR, NC, NC, 0,0,0, 1.f, 0);
    gemm_mma<<<gqkv, 256, GEMM_SMEM>>>(xdh, xdl, Wvh, Wvl, v, NB*NR, NC, NC, 0,0,0, 1.f, 0);

    // 3. norm+rope+split, v transpose+split, lambda
    normrope_split<<<(2*NB*NR*NH*2*32 + 255)/256, 256>>>(q, k, qw, kw,
        q1h,q1l,q2h,q2l,k1h,k1l,k2h,k2l);
    vtrans_split<<<(NB*NH*128*NR + 255)/256, 256>>>(v, vth, vtl);
    lambda_kernel<<<1, 32>>>(lq1, lk1, lq2, lk2, lam);

    // 4. attention scores (batched, alpha = d^-0.5)
    dim3 gsc(NR/128, NR/128, NB*NH);
    gemm_mma<<<gsc, 256, GEMM_SMEM>>>(q1h, q1l, k1h, k1l, s1, NR, NR, ND,
        (long long)NR*ND, (long long)NR*ND, (long long)NR*NR, 0.125f, 0);
    gemm_mma<<<gsc, 256, GEMM_SMEM>>>(q2h, q2l, k2h, k2l, s2, NR, NR, ND,
        (long long)NR*ND, (long long)NR*ND, (long long)NR*NR, 0.125f, 0);

    // 5. dual softmax + combine -> split probs
    softmax_combine<<<(NB*NH*NR*32 + 255)/256, 256>>>(s1, s2, lam, (ushort4*)ph, (ushort4*)pl);

    // 6. PV: diff = p @ v (batched M=512, N=128, K=512)
    dim3 gpv(1, NR/128, NB*NH);
    gemm_mma<<<gpv, 256, GEMM_SMEM>>>(ph, pl, vth, vtl, diff, NR, 128, NR,
        (long long)NR*NR, (long long)128*NR, (long long)NR*128, 1.f, 0);

    // 7. head rmsnorm * (1-lambda) -> split y
    headnorm_split<<<(NB*NH*NR*32 + 255)/256, 256>>>(diff, hw, (ushort4*)yh, (ushort4*)yl);

    // 8. Wo projection + fused silu -> lowrank_out
    gemm_mma<<<gqkv, 256, GEMM_SMEM>>>(yh, yl, Woh, Wol, lowrank, NB*NR, NC, NC, 0,0,0, 1.f, 1);

    // 9. upsample -> full_out
    upsample_kernel<<<(NB*NL*NC/4 + 255)/256, 256>>>((const float4*)lowrank, (float4*)full_out);
}

// round 5
// speedup vs baseline: 2.5810x; 1.1425x over previous
#include <cuda_runtime.h>
#include <cuda_bf16.h>
#include <math.h>
#include <stdint.h>

#define NB 4
#define NL 4096
#define NC 1024
#define NH 8
#define NR 512
#define ND 64
#define LAMBDA_INIT 0.8f
#define EPS 1e-6f

#define QKVSZ (NB*NR*NC)          // one of q,k,v (floats)
#define SZQ   (NB*NH*NR*ND)       // one of q1,q2,k1,k2 (bf16)
#define SSZ   (NB*NH*NR*NR)       // one score tensor (floats)

// ======================= device scratch (no allocs allowed) ==================
__device__ __nv_bfloat16 g_xdh[NB*NR*NC], g_xdl[NB*NR*NC];
__device__ __nv_bfloat16 g_Wh[3*NC*NC], g_Wl[3*NC*NC];       // Wq,Wk,Wv combined
__device__ __nv_bfloat16 g_Woh[NC*NC], g_Wol[NC*NC];
__device__ float g_qkv[3*QKVSZ];                              // q,k,v combined
__device__ __nv_bfloat16 g_q12h[2*SZQ], g_q12l[2*SZQ];        // q1|q2
__device__ __nv_bfloat16 g_k12h[2*SZQ], g_k12l[2*SZQ];        // k1|k2
__device__ __nv_bfloat16 g_vth[NB*NH*128*NR], g_vtl[NB*NH*128*NR];
__device__ float g_s12[2*SSZ];                                // s1|s2
__device__ __nv_bfloat16 g_ph[SSZ], g_pl[SSZ];
__device__ float g_diff[NB*NH*NR*128];
__device__ __nv_bfloat16 g_yh[NB*NR*NC], g_yl[NB*NR*NC];
__device__ float g_lam[1];

// ======================= asm helpers (all sm_80-portable) ====================
__device__ __forceinline__ uint32_t smem_u32(const void* p){
    uint32_t a;
    asm("{ .reg .u64 t; cvta.to.shared.u64 t, %1; cvt.u32.u64 %0, t; }" : "=r"(a) : "l"(p));
    return a;
}
__device__ __forceinline__ void cpa16(uint32_t d, const void* s){
    asm volatile("cp.async.cg.shared.global [%0], [%1], 16;" :: "r"(d), "l"(s));
}
#define CP_COMMIT() asm volatile("cp.async.commit_group;" ::: "memory")
#define CP_WAIT0()  asm volatile("cp.async.wait_group 0;" ::: "memory")
#define CP_WAIT1()  asm volatile("cp.async.wait_group 1;" ::: "memory")

__device__ __forceinline__ void mma16816(float* c,
    uint32_t a0, uint32_t a1, uint32_t a2, uint32_t a3, uint32_t b0, uint32_t b1)
{
    asm volatile(
        "mma.sync.aligned.m16n8k16.row.col.f32.bf16.bf16.f32 "
        "{%0,%1,%2,%3}, {%4,%5,%6,%7}, {%8,%9}, {%0,%1,%2,%3};"
        : "+f"(c[0]), "+f"(c[1]), "+f"(c[2]), "+f"(c[3])
        : "r"(a0), "r"(a1), "r"(a2), "r"(a3), "r"(b0), "r"(b1));
}
#define LDSM4(r0,r1,r2,r3, addr) \
    asm volatile("ldmatrix.sync.aligned.m8n8.x4.shared.b16 {%0,%1,%2,%3}, [%4];" \
        : "=r"(r0),"=r"(r1),"=r"(r2),"=r"(r3) : "r"(addr))

// ======================= HMMA split-bf16 batched NT GEMM =====================
// C[m,n] = alpha * sum_k (Ah+Al)[m,k]*(Bh+Bl)[n,k]   (Al*Bl dropped)
// CTA 128x128, BK=32, 8 warps (2x4), warp tile 64x32, 2-stage, 2 CTAs/SM.
#define ROW_B   80
#define TILE_B  (128*ROW_B)          // 10240
#define STG_B   (4*TILE_B)           // 40960
#define GEMM_SMEM (2*STG_B)          // 81920 -> two CTAs per SM

__device__ __forceinline__ void ld_stage(uint32_t sbase, int tid, long long c32,
    const __nv_bfloat16* Ahb, const __nv_bfloat16* Alb,
    const __nv_bfloat16* Bhb, const __nv_bfloat16* Blb, int K)
{
    int seg = tid & 3;
    #pragma unroll
    for (int it = 0; it < 8; it++) {
        int i = tid + it*256;
        int r = (i >> 2) & 127;
        const __nv_bfloat16* src =
            (it < 2) ? Ahb : (it < 4) ? Alb : (it < 6) ? Bhb : Blb;
        cpa16(sbase + (it >> 1)*TILE_B + r*ROW_B + seg*16,
              src + (long long)r*K + c32 + seg*8);
    }
    CP_COMMIT();
}

__global__ __launch_bounds__(256, 2)
void gemm_mma(const __nv_bfloat16* __restrict__ Ah, const __nv_bfloat16* __restrict__ Al,
              const __nv_bfloat16* __restrict__ Bh, const __nv_bfloat16* __restrict__ Bl,
              float* __restrict__ C, int M, int N, int K,
              long long sA, long long sB, long long sC, float alpha, int silu)
{
    extern __shared__ char sm[];
    uint32_t sb = smem_u32(sm);
    const int tid  = threadIdx.x;
    const int wid  = tid >> 5, lane = tid & 31;
    const int gid  = lane >> 2, tig = lane & 3;
    const int wm   = (wid & 1) * 64;
    const int wn   = (wid >> 1) * 32;
    const int bm   = blockIdx.y * 128, bn = blockIdx.x * 128;

    const __nv_bfloat16* Ahb = Ah + blockIdx.z*sA + (long long)bm*K;
    const __nv_bfloat16* Alb = Al + blockIdx.z*sA + (long long)bm*K;
    const __nv_bfloat16* Bhb = Bh + blockIdx.z*sB + (long long)bn*K;
    const __nv_bfloat16* Blb = Bl + blockIdx.z*sB + (long long)bn*K;
    float* Cb = C + blockIdx.z*sC;

    const int a_row = (lane & 7) + ((lane & 8)  ? 8 : 0);
    const int a_col = (lane & 16) ? 16 : 0;
    const int b_row = (lane & 7) + ((lane & 16) ? 8 : 0);
    const int b_col = (lane & 8)  ? 16 : 0;

    float acc[4][4][4];
    #pragma unroll
    for (int mi = 0; mi < 4; mi++)
        #pragma unroll
        for (int ni = 0; ni < 4; ni++)
            #pragma unroll
            for (int t = 0; t < 4; t++) acc[mi][ni][t] = 0.f;

    const int nch = K >> 5;
    ld_stage(sb, tid, 0, Ahb, Alb, Bhb, Blb, K);

    for (int c = 0; c < nch; c++) {
        if (c + 1 < nch) {
            ld_stage(sb + ((c + 1) & 1)*STG_B, tid, (long long)(c + 1)*32,
                     Ahb, Alb, Bhb, Blb, K);
            CP_WAIT1();
        } else {
            CP_WAIT0();
        }
        __syncthreads();

        const uint32_t p = sb + (c & 1)*STG_B;
        const uint32_t pAh = p,            pAl = p +   TILE_B;
        const uint32_t pBh = p + 2*TILE_B, pBl = p + 3*TILE_B;

        #pragma unroll
        for (int kk = 0; kk < 2; kk++) {
            const int ko = kk*32;
            // load B fragments once per k-step (16 regs live)
            uint32_t bh[4][2], bl[4][2];
            #pragma unroll
            for (int nj = 0; nj < 2; nj++) {
                uint32_t bd = pBh + (wn + nj*16 + b_row)*ROW_B + ko + b_col;
                LDSM4(bh[2*nj][0], bh[2*nj][1], bh[2*nj+1][0], bh[2*nj+1][1], bd);
                uint32_t bd2 = pBl + (wn + nj*16 + b_row)*ROW_B + ko + b_col;
                LDSM4(bl[2*nj][0], bl[2*nj][1], bl[2*nj+1][0], bl[2*nj+1][1], bd2);
            }
            // stream A fragments per mi (8 regs transient)
            #pragma unroll
            for (int mi = 0; mi < 4; mi++) {
                uint32_t ah[4], al[4];
                uint32_t ad  = pAh + (wm + mi*16 + a_row)*ROW_B + ko + a_col;
                LDSM4(ah[0], ah[1], ah[2], ah[3], ad);
                uint32_t ad2 = pAl + (wm + mi*16 + a_row)*ROW_B + ko + a_col;
                LDSM4(al[0], al[1], al[2], al[3], ad2);
                #pragma unroll
                for (int ni = 0; ni < 4; ni++) {
                    mma16816(acc[mi][ni], ah[0], ah[1], ah[2], ah[3], bh[ni][0], bh[ni][1]);
                    mma16816(acc[mi][ni], al[0], al[1], al[2], al[3], bh[ni][0], bh[ni][1]);
                    mma16816(acc[mi][ni], ah[0], ah[1], ah[2], ah[3], bl[ni][0], bl[ni][1]);
                }
            }
        }
        __syncthreads();
    }

    #pragma unroll
    for (int mi = 0; mi < 4; mi++) {
        #pragma unroll
        for (int ni = 0; ni < 4; ni++) {
            int row = bm + wm + mi*16 + gid;
            int col = bn + wn + ni*8 + tig*2;
            float v0 = acc[mi][ni][0]*alpha, v1 = acc[mi][ni][1]*alpha;
            float v2 = acc[mi][ni][2]*alpha, v3 = acc[mi][ni][3]*alpha;
            if (silu) {
                v0 /= (1.f + expf(-v0)); v1 /= (1.f + expf(-v1));
                v2 /= (1.f + expf(-v2)); v3 /= (1.f + expf(-v3));
            }
            *(float2*)&Cb[(long long)row*N + col]       = make_float2(v0, v1);
            *(float2*)&Cb[(long long)(row + 8)*N + col] = make_float2(v2, v3);
        }
    }
}

// ======================= split helpers =======================================
__device__ __forceinline__ void split1(float v, unsigned short& h, unsigned short& l){
    __nv_bfloat16 hb = __float2bfloat16(v);
    __nv_bfloat16 lb = __float2bfloat16(v - __bfloat162float(hb));
    h = __bfloat16_as_ushort(hb); l = __bfloat16_as_ushort(lb);
}

__global__ void downsample_split(const float4* __restrict__ x,
                                 ushort4* __restrict__ xh, ushort4* __restrict__ xl)
{
    int idx = blockIdx.x*blockDim.x + threadIdx.x;
    if (idx >= NB*NR*NC/4) return;
    int c4 = idx & 255, bi = idx >> 8;
    int i = bi & (NR-1), b = bi >> 9;
    long long row = (long long)b*NL + 8*i + 3;
    float4 p = x[row*256 + c4], q = x[(row+1)*256 + c4];
    float v0 = 0.5f*(p.x+q.x), v1 = 0.5f*(p.y+q.y), v2 = 0.5f*(p.z+q.z), v3 = 0.5f*(p.w+q.w);
    ushort4 h, l;
    split1(v0, h.x, l.x); split1(v1, h.y, l.y); split1(v2, h.z, l.z); split1(v3, h.w, l.w);
    xh[idx] = h; xl[idx] = l;
}

// Wq,Wk,Wv -> combined g_Wh/g_Wl; Wo -> g_Woh/g_Wol
__global__ void convert_split4(const float4* __restrict__ Wq, const float4* __restrict__ Wk,
                               const float4* __restrict__ Wv, const float4* __restrict__ Wo,
                               ushort4* __restrict__ wh, ushort4* __restrict__ wl,
                               ushort4* __restrict__ oh, ushort4* __restrict__ ol)
{
    int idx = blockIdx.x*blockDim.x + threadIdx.x;
    if (idx >= NC*NC/4) return;
    const float4* s; ushort4 *dh, *dl; int off = 0;
    switch (blockIdx.y) {
        case 0: s = Wq; dh = wh; dl = wl; off = 0;          break;
        case 1: s = Wk; dh = wh; dl = wl; off = NC*NC/4;    break;
        case 2: s = Wv; dh = wh; dl = wl; off = 2*(NC*NC/4);break;
        default:s = Wo; dh = oh; dl = ol; off = 0;          break;
    }
    float4 v = s[idx];
    ushort4 h, l;
    split1(v.x, h.x, l.x); split1(v.y, h.y, l.y); split1(v.z, h.z, l.z); split1(v.w, h.w, l.w);
    dh[off + idx] = h; dl[off + idx] = l;
}

// rmsnorm(64) + rope(pos = head idx) + split; writes into q12/k12 halves
__global__ void normrope_split(const float* __restrict__ qb, const float* __restrict__ kb,
                               const float* __restrict__ qw, const float* __restrict__ kw,
                               __nv_bfloat16* __restrict__ q12h, __nv_bfloat16* __restrict__ q12l,
                               __nv_bfloat16* __restrict__ k12h, __nv_bfloat16* __restrict__ k12l)
{
    int gw   = (blockIdx.x*blockDim.x + threadIdx.x) >> 5;
    int lane = threadIdx.x & 31;
    const int NROWS = NB*NR*NH*2;
    if (gw >= 2*NROWS) return;
    int isK = gw >= NROWS;
    int row = isK ? (gw - NROWS) : gw;
    const float* src = (isK ? kb : qb) + (long long)row * 64;
    float x1 = src[lane], x2 = src[lane+32];
    float ss = x1*x1 + x2*x2;
    #pragma unroll
    for (int o = 16; o; o >>= 1) ss += __shfl_xor_sync(0xffffffffu, ss, o);
    float inv = 1.f / sqrtf(ss*(1.f/64.f) + EPS);
    const float* w = isK ? kw : qw;
    float n1 = x1*inv*w[lane], n2 = x2*inv*w[lane+32];
    int s  = row & 1;
    int h  = (row >> 1) & 7;
    int bi = row >> 4;
    int b  = bi >> 9, i = bi & 511;
    float f = powf(10000.f, -(float)lane * (1.f/32.f));
    float sn, cs; sincosf((float)h * f, &sn, &cs);
    float o1 = n1*cs - n2*sn, o2 = n1*sn + n2*cs;
    __nv_bfloat16* dh = (isK ? k12h : q12h) + (long long)s*SZQ;
    __nv_bfloat16* dl = (isK ? k12l : q12l) + (long long)s*SZQ;
    long long off = ((long long)((b*NH + h)*NR) + i) * 64;
    unsigned short hh, ll;
    split1(o1, hh, ll); dh[off+lane]    = __ushort_as_bfloat16(hh); dl[off+lane]    = __ushort_as_bfloat16(ll);
    split1(o2, hh, ll); dh[off+lane+32] = __ushort_as_bfloat16(hh); dl[off+lane+32] = __ushort_as_bfloat16(ll);
}

__global__ void vtrans_split(const float* __restrict__ v,
                             __nv_bfloat16* __restrict__ vth, __nv_bfloat16* __restrict__ vtl)
{
    int idx = blockIdx.x*blockDim.x + threadIdx.x;
    if (idx >= NB*NH*128*NR) return;
    int i = idx & 511, c = (idx >> 9) & 127, bh = idx >> 16;
    int b = bh >> 3, h = bh & 7;
    float vv = v[((long long)(b*NR + i))*NC + h*128 + c];
    unsigned short hh, ll; split1(vv, hh, ll);
    vth[idx] = __ushort_as_bfloat16(hh); vtl[idx] = __ushort_as_bfloat16(ll);
}

__global__ void lambda_kernel(const float* lq1, const float* lk1,
                              const float* lq2, const float* lk2, float* out)
{
    int t = threadIdx.x;
    float a = lq1[t]*lk1[t] + lq1[t+32]*lk1[t+32];
    float b = lq2[t]*lk2[t] + lq2[t+32]*lk2[t+32];
    #pragma unroll
    for (int o = 16; o; o >>= 1) {
        a += __shfl_xor_sync(0xffffffffu, a, o);
        b += __shfl_xor_sync(0xffffffffu, b, o);
    }
    if (t == 0) out[0] = expf(a) - expf(b) + LAMBDA_INIT;
}

// dual softmax + combine -> split bf16 probs (s1 = s12[0:], s2 = s12[SSZ:])
__global__ void softmax_combine(const float* __restrict__ s12,
                                const float* __restrict__ lamp,
                                ushort4* __restrict__ ph, ushort4* __restrict__ pl)
{
    int gw   = (blockIdx.x*blockDim.x + threadIdx.x) >> 5;
    int lane = threadIdx.x & 31;
    if (gw >= NB*NH*NR) return;
    const float4* r1 = (const float4*)(s12 + (long long)gw * NR);
    const float4* r2 = (const float4*)(s12 + (long long)SSZ + (long long)gw * NR);
    float4 v1[4], v2[4];
    float m1 = -1e30f, m2 = -1e30f;
    #pragma unroll
    for (int i = 0; i < 4; i++) {
        v1[i] = r1[lane + 32*i]; v2[i] = r2[lane + 32*i];
        m1 = fmaxf(m1, fmaxf(fmaxf(v1[i].x, v1[i].y), fmaxf(v1[i].z, v1[i].w)));
        m2 = fmaxf(m2, fmaxf(fmaxf(v2[i].x, v2[i].y), fmaxf(v2[i].z, v2[i].w)));
    }
    #pragma unroll
    for (int o = 16; o; o >>= 1) {
        m1 = fmaxf(m1, __shfl_xor_sync(0xffffffffu, m1, o));
        m2 = fmaxf(m2, __shfl_xor_sync(0xffffffffu, m2, o));
    }
    float a1 = 0.f, a2 = 0.f;
    #pragma unroll
    for (int i = 0; i < 4; i++) {
        v1[i].x = expf(v1[i].x-m1); v1[i].y = expf(v1[i].y-m1);
        v1[i].z = expf(v1[i].z-m1); v1[i].w = expf(v1[i].w-m1);
        v2[i].x = expf(v2[i].x-m2); v2[i].y = expf(v2[i].y-m2);
        v2[i].z = expf(v2[i].z-m2); v2[i].w = expf(v2[i].w-m2);
        a1 += v1[i].x+v1[i].y+v1[i].z+v1[i].w;
        a2 += v2[i].x+v2[i].y+v2[i].z+v2[i].w;
    }
    #pragma unroll
    for (int o = 16; o; o >>= 1) {
        a1 += __shfl_xor_sync(0xffffffffu, a1, o);
        a2 += __shfl_xor_sync(0xffffffffu, a2, o);
    }
    float is1 = 1.f/a1, is2 = lamp[0]/a2;
    #pragma unroll
    for (int i = 0; i < 4; i++) {
        float o0 = v1[i].x*is1 - v2[i].x*is2;
        float o1 = v1[i].y*is1 - v2[i].y*is2;
        float o2 = v1[i].z*is1 - v2[i].z*is2;
        float o3 = v1[i].w*is1 - v2[i].w*is2;
        ushort4 h, l;
        split1(o0,h.x,l.x); split1(o1,h.y,l.y); split1(o2,h.z,l.z); split1(o3,h.w,l.w);
        ph[(long long)gw*128 + lane + 32*i] = h;
        pl[(long long)gw*128 + lane + 32*i] = l;
    }
}

// head rmsnorm(128) * (1-lambda_init) -> (B,r,C) layout, split bf16
__global__ void headnorm_split(const float* __restrict__ diff, const float* __restrict__ hw,
                               ushort4* __restrict__ yh, ushort4* __restrict__ yl)
{
    int gw   = (blockIdx.x*blockDim.x + threadIdx.x) >> 5;
    int lane = threadIdx.x & 31;
    if (gw >= NB*NH*NR) return;
    const float4* src = (const float4*)(diff + (long long)gw * 128);
    float4 a = src[lane];
    float ss = a.x*a.x + a.y*a.y + a.z*a.z + a.w*a.w;
    #pragma unroll
    for (int o = 16; o; o >>= 1) ss += __shfl_xor_sync(0xffffffffu, ss, o);
    float inv = (1.f - LAMBDA_INIT) / sqrtf(ss*(1.f/128.f) + EPS);
    int bh = gw >> 9, i = gw & 511;
    int b = bh >> 3, h = bh & 7;
    float4 w = ((const float4*)hw)[lane];
    float o0 = a.x*inv*w.x, o1 = a.y*inv*w.y, o2 = a.z*inv*w.z, o3 = a.w*inv*w.w;
    ushort4 hh, ll;
    split1(o0,hh.x,ll.x); split1(o1,hh.y,ll.y); split1(o2,hh.z,ll.z); split1(o3,hh.w,ll.w);
    long long oidx = (long long)(b*NR + i)*256 + h*32 + lane;
    yh[oidx] = hh; yl[oidx] = ll;
}

// upsample 512 -> 4096
__global__ void upsample_kernel(const float4* __restrict__ lr, float4* __restrict__ out)
{
    int idx = blockIdx.x*blockDim.x + threadIdx.x;
    if (idx >= NB*NL*NC/4) return;
    int c4 = idx & 255, j = (idx >> 8) & (NL-1), b = idx >> 20;
    float coords = fminf(fmaxf(((float)j + 0.5f)*0.125f - 0.5f, 0.f), 511.f);
    int lo = (int)coords;
    int hi = min(lo + 1, 511);
    float w = coords - (float)lo, w0 = 1.f - w;
    long long base = (long long)b * NR * 256;
    float4 a = lr[base + (long long)lo*256 + c4];
    float4 c = lr[base + (long long)hi*256 + c4];
    float4 o;
    o.x = a.x*w0 + c.x*w; o.y = a.y*w0 + c.y*w;
    o.z = a.z*w0 + c.z*w; o.w = a.w*w0 + c.w*w;
    out[idx] = o;
}

// ======================= host launcher =======================================
extern "C" void kernel_launch(void* const* d_in, const int* in_sizes, int n_in,
                              void* d_out, int out_size)
{
    const float* x   = (const float*)d_in[0];
    const float* Wq  = (const float*)d_in[1];
    const float* Wk  = (const float*)d_in[2];
    const float* Wv  = (const float*)d_in[3];
    const float* Wo  = (const float*)d_in[4];
    const float* qw  = (const float*)d_in[5];
    const float* kw  = (const float*)d_in[6];
    const float* hw  = (const float*)d_in[7];
    const float* lq1 = (const float*)d_in[8];
    const float* lk1 = (const float*)d_in[9];
    const float* lq2 = (const float*)d_in[10];
    const float* lk2 = (const float*)d_in[11];

    float* full_out = (float*)d_out;
    float* lowrank  = full_out + (size_t)NB*NL*NC;

    #define GS(p, s) cudaGetSymbolAddress((void**)&p, s)
    __nv_bfloat16 *xdh,*xdl,*Wh,*Wl,*Woh,*Wol;
    __nv_bfloat16 *q12h,*q12l,*k12h,*k12l,*vth,*vtl,*ph,*pl,*yh,*yl;
    float *qkv,*s12,*diff,*lam;
    GS(xdh,g_xdh); GS(xdl,g_xdl);
    GS(Wh,g_Wh); GS(Wl,g_Wl); GS(Woh,g_Woh); GS(Wol,g_Wol);
    GS(qkv,g_qkv);
    GS(q12h,g_q12h); GS(q12l,g_q12l); GS(k12h,g_k12h); GS(k12l,g_k12l);
    GS(vth,g_vth); GS(vtl,g_vtl);
    GS(s12,g_s12); GS(ph,g_ph); GS(pl,g_pl);
    GS(diff,g_diff); GS(yh,g_yh); GS(yl,g_yl); GS(lam,g_lam);
    #undef GS

    cudaFuncSetAttribute(gemm_mma, cudaFuncAttributeMaxDynamicSharedMemorySize, GEMM_SMEM);

    // 1. downsample + split; weights split (one fused launch)
    downsample_split<<<(NB*NR*NC/4 + 255)/256, 256>>>((const float4*)x, (ushort4*)xdh, (ushort4*)xdl);
    dim3 gcv((NC*NC/4 + 255)/256, 4);
    convert_split4<<<gcv, 256>>>((const float4*)Wq, (const float4*)Wk,
                                 (const float4*)Wv, (const float4*)Wo,
                                 (ushort4*)Wh, (ushort4*)Wl, (ushort4*)Woh, (ushort4*)Wol);

    // 2. QKV projections: ONE launch, grid.z selects weight/output (384 CTAs)
    dim3 gqkv(NC/128, (NB*NR)/128, 3);
    gemm_mma<<<gqkv, 256, GEMM_SMEM>>>(xdh, xdl, Wh, Wl, qkv, NB*NR, NC, NC,
        0, (long long)NC*NC, (long long)QKVSZ, 1.f, 0);

    // 3. norm+rope+split, v transpose+split, lambda
    normrope_split<<<(2*NB*NR*NH*2*32 + 255)/256, 256>>>(qkv, qkv + QKVSZ, qw, kw,
        q12h, q12l, k12h, k12l);
    vtrans_split<<<(NB*NH*128*NR + 255)/256, 256>>>(qkv + 2*QKVSZ, vth, vtl);
    lambda_kernel<<<1, 32>>>(lq1, lk1, lq2, lk2, lam);

    // 4. both score GEMMs: ONE launch, z in [0,64) spans s1|s2 (1024 CTAs)
    dim3 gsc(NR/128, NR/128, 2*NB*NH);
    gemm_mma<<<gsc, 256, GEMM_SMEM>>>(q12h, q12l, k12h, k12l, s12, NR, NR, ND,
        (long long)NR*ND, (long long)NR*ND, (long long)NR*NR, 0.125f, 0);

    // 5. dual softmax + combine -> split probs
    softmax_combine<<<(NB*NH*NR*32 + 255)/256, 256>>>(s12, lam, (ushort4*)ph, (ushort4*)pl);

    // 6. PV: diff = p @ v (batched M=512, N=128, K=512)
    dim3 gpv(1, NR/128, NB*NH);
    gemm_mma<<<gpv, 256, GEMM_SMEM>>>(ph, pl, vth, vtl, diff, NR, 128, NR,
        (long long)NR*NR, (long long)128*NR, (long long)NR*128, 1.f, 0);

    // 7. head rmsnorm * (1-lambda) -> split y
    headnorm_split<<<(NB*NH*NR*32 + 255)/256, 256>>>(diff, hw, (ushort4*)yh, (ushort4*)yl);

    // 8. Wo projection + fused silu -> lowrank_out
    dim3 gwo(NC/128, (NB*NR)/128, 1);
    gemm_mma<<<gwo, 256, GEMM_SMEM>>>(yh, yl, Woh, Wol, lowrank, NB*NR, NC, NC,
        0, 0, 0, 1.f, 1);

    // 9. upsample -> full_out
    upsample_kernel<<<(NB*NL*NC/4 + 255)/256, 256>>>((const float4*)lowrank, (float4*)full_out);
}

// round 6
// speedup vs baseline: 2.7255x; 1.0560x over previous
#include <cuda_runtime.h>
#include <cuda_bf16.h>
#include <math.h>
#include <stdint.h>

#define NB 4
#define NL 4096
#define NC 1024
#define NH 8
#define NR 512
#define ND 64
#define LAMBDA_INIT 0.8f
#define EPS 1e-6f

#define QKVSZ (NB*NR*NC)
#define SZQ   (NB*NH*NR*ND)
#define SSZ   (NB*NH*NR*NR)

// ======================= device scratch (no allocs allowed) ==================
__device__ __nv_bfloat16 g_xdh[NB*NR*NC], g_xdl[NB*NR*NC];
__device__ __nv_bfloat16 g_Wh[3*NC*NC], g_Wl[3*NC*NC];
__device__ __nv_bfloat16 g_Woh[NC*NC], g_Wol[NC*NC];
__device__ float g_qkv[3*QKVSZ];
__device__ __nv_bfloat16 g_q12h[2*SZQ], g_q12l[2*SZQ];
__device__ __nv_bfloat16 g_k12h[2*SZQ], g_k12l[2*SZQ];
__device__ __nv_bfloat16 g_vth[NB*NH*128*NR], g_vtl[NB*NH*128*NR];
__device__ float g_s12[2*SSZ];
__device__ __nv_bfloat16 g_ph[SSZ], g_pl[SSZ];
__device__ __nv_bfloat16 g_yh[NB*NR*NC], g_yl[NB*NR*NC];
__device__ float g_lam[1];

// ======================= asm helpers =========================================
__device__ __forceinline__ uint32_t smem_u32(const void* p){
    uint32_t a;
    asm("{ .reg .u64 t; cvta.to.shared.u64 t, %1; cvt.u32.u64 %0, t; }" : "=r"(a) : "l"(p));
    return a;
}
__device__ __forceinline__ void cpa16(uint32_t d, const void* s){
    asm volatile("cp.async.cg.shared.global [%0], [%1], 16;" :: "r"(d), "l"(s));
}
#define CP_COMMIT() asm volatile("cp.async.commit_group;" ::: "memory")
#define CP_WAIT0()  asm volatile("cp.async.wait_group 0;" ::: "memory")
#define CP_WAIT1()  asm volatile("cp.async.wait_group 1;" ::: "memory")

__device__ __forceinline__ void mma16816(float* c,
    uint32_t a0, uint32_t a1, uint32_t a2, uint32_t a3, uint32_t b0, uint32_t b1)
{
    asm volatile(
        "mma.sync.aligned.m16n8k16.row.col.f32.bf16.bf16.f32 "
        "{%0,%1,%2,%3}, {%4,%5,%6,%7}, {%8,%9}, {%0,%1,%2,%3};"
        : "+f"(c[0]), "+f"(c[1]), "+f"(c[2]), "+f"(c[3])
        : "r"(a0), "r"(a1), "r"(a2), "r"(a3), "r"(b0), "r"(b1));
}
#define LDSM4(r0,r1,r2,r3, addr) \
    asm volatile("ldmatrix.sync.aligned.m8n8.x4.shared.b16 {%0,%1,%2,%3}, [%4];" \
        : "=r"(r0),"=r"(r1),"=r"(r2),"=r"(r3) : "r"(addr))

__device__ __forceinline__ void split1(float v, unsigned short& h, unsigned short& l){
    __nv_bfloat16 hb = __float2bfloat16(v);
    __nv_bfloat16 lb = __float2bfloat16(v - __bfloat162float(hb));
    h = __bfloat16_as_ushort(hb); l = __bfloat16_as_ushort(lb);
}

// ======================= HMMA split-bf16 batched NT GEMM =====================
// mode 0: C = alpha*acc     mode 1: C = silu(acc)     mode 2: fused headnorm->yh/yl
#define ROW_B   80
#define TILE_B  (128*ROW_B)
#define STG_B   (4*TILE_B)
#define GEMM_SMEM (2*STG_B)          // 81920 -> 2 CTAs/SM

__device__ __forceinline__ void ld_stage(uint32_t sbase, int tid, long long c32,
    const __nv_bfloat16* Ahb, const __nv_bfloat16* Alb,
    const __nv_bfloat16* Bhb, const __nv_bfloat16* Blb, int K)
{
    int seg = tid & 3;
    #pragma unroll
    for (int it = 0; it < 8; it++) {
        int i = tid + it*256;
        int r = (i >> 2) & 127;
        const __nv_bfloat16* src =
            (it < 2) ? Ahb : (it < 4) ? Alb : (it < 6) ? Bhb : Blb;
        cpa16(sbase + (it >> 1)*TILE_B + r*ROW_B + seg*16,
              src + (long long)r*K + c32 + seg*8);
    }
    CP_COMMIT();
}

__global__ __launch_bounds__(256, 2)
void gemm_mma(const __nv_bfloat16* __restrict__ Ah, const __nv_bfloat16* __restrict__ Al,
              const __nv_bfloat16* __restrict__ Bh, const __nv_bfloat16* __restrict__ Bl,
              float* __restrict__ C, int M, int N, int K,
              long long sA, long long sB, long long sC, float alpha, int mode,
              const float* __restrict__ hw,
              __nv_bfloat16* __restrict__ yh, __nv_bfloat16* __restrict__ yl)
{
    extern __shared__ char sm[];
    uint32_t sb = smem_u32(sm);
    const int tid  = threadIdx.x;
    const int wid  = tid >> 5, lane = tid & 31;
    const int gid  = lane >> 2, tig = lane & 3;
    const int wm   = (wid & 1) * 64;
    const int wn   = (wid >> 1) * 32;
    const int bm   = blockIdx.y * 128, bn = blockIdx.x * 128;

    const __nv_bfloat16* Ahb = Ah + blockIdx.z*sA + (long long)bm*K;
    const __nv_bfloat16* Alb = Al + blockIdx.z*sA + (long long)bm*K;
    const __nv_bfloat16* Bhb = Bh + blockIdx.z*sB + (long long)bn*K;
    const __nv_bfloat16* Blb = Bl + blockIdx.z*sB + (long long)bn*K;

    const int a_row = (lane & 7) + ((lane & 8)  ? 8 : 0);
    const int a_col = (lane & 16) ? 16 : 0;
    const int b_row = (lane & 7) + ((lane & 16) ? 8 : 0);
    const int b_col = (lane & 8)  ? 16 : 0;

    float acc[4][4][4];
    #pragma unroll
    for (int mi = 0; mi < 4; mi++)
        #pragma unroll
        for (int ni = 0; ni < 4; ni++)
            #pragma unroll
            for (int t = 0; t < 4; t++) acc[mi][ni][t] = 0.f;

    const int nch = K >> 5;
    ld_stage(sb, tid, 0, Ahb, Alb, Bhb, Blb, K);

    for (int c = 0; c < nch; c++) {
        if (c + 1 < nch) {
            ld_stage(sb + ((c + 1) & 1)*STG_B, tid, (long long)(c + 1)*32,
                     Ahb, Alb, Bhb, Blb, K);
            CP_WAIT1();
        } else {
            CP_WAIT0();
        }
        __syncthreads();

        const uint32_t p = sb + (c & 1)*STG_B;
        const uint32_t pAh = p,            pAl = p +   TILE_B;
        const uint32_t pBh = p + 2*TILE_B, pBl = p + 3*TILE_B;

        #pragma unroll
        for (int kk = 0; kk < 2; kk++) {
            const int ko = kk*32;
            uint32_t bh[4][2], bl[4][2];
            #pragma unroll
            for (int nj = 0; nj < 2; nj++) {
                uint32_t bd = pBh + (wn + nj*16 + b_row)*ROW_B + ko + b_col;
                LDSM4(bh[2*nj][0], bh[2*nj][1], bh[2*nj+1][0], bh[2*nj+1][1], bd);
                uint32_t bd2 = pBl + (wn + nj*16 + b_row)*ROW_B + ko + b_col;
                LDSM4(bl[2*nj][0], bl[2*nj][1], bl[2*nj+1][0], bl[2*nj+1][1], bd2);
            }
            #pragma unroll
            for (int mi = 0; mi < 4; mi++) {
                uint32_t ah[4], al[4];
                uint32_t ad  = pAh + (wm + mi*16 + a_row)*ROW_B + ko + a_col;
                LDSM4(ah[0], ah[1], ah[2], ah[3], ad);
                uint32_t ad2 = pAl + (wm + mi*16 + a_row)*ROW_B + ko + a_col;
                LDSM4(al[0], al[1], al[2], al[3], ad2);
                #pragma unroll
                for (int ni = 0; ni < 4; ni++) {
                    mma16816(acc[mi][ni], ah[0], ah[1], ah[2], ah[3], bh[ni][0], bh[ni][1]);
                    mma16816(acc[mi][ni], al[0], al[1], al[2], al[3], bh[ni][0], bh[ni][1]);
                    mma16816(acc[mi][ni], ah[0], ah[1], ah[2], ah[3], bl[ni][0], bl[ni][1]);
                }
            }
        }
        __syncthreads();
    }

    if (mode != 2) {
        float* Cb = C + blockIdx.z*sC;
        #pragma unroll
        for (int mi = 0; mi < 4; mi++) {
            #pragma unroll
            for (int ni = 0; ni < 4; ni++) {
                int row = bm + wm + mi*16 + gid;
                int col = bn + wn + ni*8 + tig*2;
                float v0 = acc[mi][ni][0]*alpha, v1 = acc[mi][ni][1]*alpha;
                float v2 = acc[mi][ni][2]*alpha, v3 = acc[mi][ni][3]*alpha;
                if (mode == 1) {
                    v0 /= (1.f + __expf(-v0)); v1 /= (1.f + __expf(-v1));
                    v2 /= (1.f + __expf(-v2)); v3 /= (1.f + __expf(-v3));
                }
                *(float2*)&Cb[(long long)row*N + col]       = make_float2(v0, v1);
                *(float2*)&Cb[(long long)(row + 8)*N + col] = make_float2(v2, v3);
            }
        }
        return;
    }

    // ---------- mode 2: fused head rmsnorm (N==128 tile spans the head) ------
    float* esm = (float*)sm;   // 128 rows x 132 floats
    #pragma unroll
    for (int mi = 0; mi < 4; mi++) {
        #pragma unroll
        for (int ni = 0; ni < 4; ni++) {
            int r0 = wm + mi*16 + gid;
            int cc = wn + ni*8 + tig*2;
            esm[r0*132 + cc]     = acc[mi][ni][0];
            esm[r0*132 + cc + 1] = acc[mi][ni][1];
            esm[(r0+8)*132 + cc]     = acc[mi][ni][2];
            esm[(r0+8)*132 + cc + 1] = acc[mi][ni][3];
        }
    }
    __syncthreads();

    const int z = blockIdx.z, b = z >> 3, h = z & 7;
    for (int r = wid; r < 128; r += 8) {
        float4 vv = *(float4*)&esm[r*132 + lane*4];
        float ssq = vv.x*vv.x + vv.y*vv.y + vv.z*vv.z + vv.w*vv.w;
        #pragma unroll
        for (int o = 16; o; o >>= 1) ssq += __shfl_xor_sync(0xffffffffu, ssq, o);
        float inv = (1.f - LAMBDA_INIT) * rsqrtf(ssq*(1.f/128.f) + EPS);
        float4 w = ((const float4*)hw)[lane];
        float o0 = vv.x*inv*w.x, o1 = vv.y*inv*w.y, o2 = vv.z*inv*w.z, o3 = vv.w*inv*w.w;
        ushort4 hh, ll;
        split1(o0,hh.x,ll.x); split1(o1,hh.y,ll.y); split1(o2,hh.z,ll.z); split1(o3,hh.w,ll.w);
        int i = bm + r;
        long long o4 = (long long)(b*NR + i)*256 + h*32 + lane;
        ((ushort4*)yh)[o4] = hh;
        ((ushort4*)yl)[o4] = ll;
    }
}

// ======================= elementwise kernels =================================
__global__ void downsample_split(const float4* __restrict__ x,
                                 ushort4* __restrict__ xh, ushort4* __restrict__ xl)
{
    int idx = blockIdx.x*blockDim.x + threadIdx.x;
    if (idx >= NB*NR*NC/4) return;
    int c4 = idx & 255, bi = idx >> 8;
    int i = bi & (NR-1), b = bi >> 9;
    long long row = (long long)b*NL + 8*i + 3;
    float4 p = x[row*256 + c4], q = x[(row+1)*256 + c4];
    float v0 = 0.5f*(p.x+q.x), v1 = 0.5f*(p.y+q.y), v2 = 0.5f*(p.z+q.z), v3 = 0.5f*(p.w+q.w);
    ushort4 h, l;
    split1(v0, h.x, l.x); split1(v1, h.y, l.y); split1(v2, h.z, l.z); split1(v3, h.w, l.w);
    xh[idx] = h; xl[idx] = l;
}

__global__ void convert_split4(const float4* __restrict__ Wq, const float4* __restrict__ Wk,
                               const float4* __restrict__ Wv, const float4* __restrict__ Wo,
                               ushort4* __restrict__ wh, ushort4* __restrict__ wl,
                               ushort4* __restrict__ oh, ushort4* __restrict__ ol)
{
    int idx = blockIdx.x*blockDim.x + threadIdx.x;
    if (idx >= NC*NC/4) return;
    const float4* s; ushort4 *dh, *dl; int off = 0;
    switch (blockIdx.y) {
        case 0: s = Wq; dh = wh; dl = wl; off = 0;          break;
        case 1: s = Wk; dh = wh; dl = wl; off = NC*NC/4;    break;
        case 2: s = Wv; dh = wh; dl = wl; off = 2*(NC*NC/4);break;
        default:s = Wo; dh = oh; dl = ol; off = 0;          break;
    }
    float4 v = s[idx];
    ushort4 h, l;
    split1(v.x, h.x, l.x); split1(v.y, h.y, l.y); split1(v.z, h.z, l.z); split1(v.w, h.w, l.w);
    dh[off + idx] = h; dl[off + idx] = l;
}

// rmsnorm(64) + rope(pos = head idx) + split (fast transcendentals)
__global__ void normrope_split(const float* __restrict__ qb, const float* __restrict__ kb,
                               const float* __restrict__ qw, const float* __restrict__ kw,
                               __nv_bfloat16* __restrict__ q12h, __nv_bfloat16* __restrict__ q12l,
                               __nv_bfloat16* __restrict__ k12h, __nv_bfloat16* __restrict__ k12l)
{
    int gw   = (blockIdx.x*blockDim.x + threadIdx.x) >> 5;
    int lane = threadIdx.x & 31;
    const int NROWS = NB*NR*NH*2;
    if (gw >= 2*NROWS) return;
    int isK = gw >= NROWS;
    int row = isK ? (gw - NROWS) : gw;
    const float* src = (isK ? kb : qb) + (long long)row * 64;
    float x1 = src[lane], x2 = src[lane+32];
    float ss = x1*x1 + x2*x2;
    #pragma unroll
    for (int o = 16; o; o >>= 1) ss += __shfl_xor_sync(0xffffffffu, ss, o);
    float inv = rsqrtf(ss*(1.f/64.f) + EPS);
    const float* w = isK ? kw : qw;
    float n1 = x1*inv*w[lane], n2 = x2*inv*w[lane+32];
    int s  = row & 1;
    int h  = (row >> 1) & 7;
    int bi = row >> 4;
    int b  = bi >> 9, i = bi & 511;
    // f = 10000^(-lane/32) = exp2(-lane * log2(10000)/32)
    float f = exp2f(-0.41524101186351494f * (float)lane);
    float sn, cs; __sincosf((float)h * f, &sn, &cs);
    float o1 = n1*cs - n2*sn, o2 = n1*sn + n2*cs;
    __nv_bfloat16* dh = (isK ? k12h : q12h) + (long long)s*SZQ;
    __nv_bfloat16* dl = (isK ? k12l : q12l) + (long long)s*SZQ;
    long long off = ((long long)((b*NH + h)*NR) + i) * 64;
    unsigned short hh, ll;
    split1(o1, hh, ll); dh[off+lane]    = __ushort_as_bfloat16(hh); dl[off+lane]    = __ushort_as_bfloat16(ll);
    split1(o2, hh, ll); dh[off+lane+32] = __ushort_as_bfloat16(hh); dl[off+lane+32] = __ushort_as_bfloat16(ll);
}

// v transpose via smem tiles: (b,i,h*128+c) -> (bh, c, i), split bf16
__global__ void vtrans_split(const float* __restrict__ v,
                             __nv_bfloat16* __restrict__ vth, __nv_bfloat16* __restrict__ vtl)
{
    __shared__ float t[32][33];
    const int tx = threadIdx.x, ty = threadIdx.y;     // 32 x 8
    const int bh = blockIdx.z, b = bh >> 3, h = bh & 7;
    const int c0 = blockIdx.x*32, i0 = blockIdx.y*32;
    #pragma unroll
    for (int jj = 0; jj < 4; jj++) {
        int r = ty + jj*8;
        t[r][tx] = v[(long long)(b*NR + i0 + r)*NC + h*128 + c0 + tx];
    }
    __syncthreads();
    #pragma unroll
    for (int jj = 0; jj < 4; jj++) {
        int cc = ty + jj*8;
        float val = t[tx][cc];
        unsigned short hh, ll; split1(val, hh, ll);
        long long o = (long long)(bh*128 + c0 + cc)*NR + i0 + tx;
        vth[o] = __ushort_as_bfloat16(hh);
        vtl[o] = __ushort_as_bfloat16(ll);
    }
}

__global__ void lambda_kernel(const float* lq1, const float* lk1,
                              const float* lq2, const float* lk2, float* out)
{
    int t = threadIdx.x;
    float a = lq1[t]*lk1[t] + lq1[t+32]*lk1[t+32];
    float b = lq2[t]*lk2[t] + lq2[t+32]*lk2[t+32];
    #pragma unroll
    for (int o = 16; o; o >>= 1) {
        a += __shfl_xor_sync(0xffffffffu, a, o);
        b += __shfl_xor_sync(0xffffffffu, b, o);
    }
    if (t == 0) out[0] = expf(a) - expf(b) + LAMBDA_INIT;
}

// dual softmax + combine -> split bf16 probs
__global__ void softmax_combine(const float* __restrict__ s12,
                                const float* __restrict__ lamp,
                                ushort4* __restrict__ ph, ushort4* __restrict__ pl)
{
    int gw   = (blockIdx.x*blockDim.x + threadIdx.x) >> 5;
    int lane = threadIdx.x & 31;
    if (gw >= NB*NH*NR) return;
    const float4* r1 = (const float4*)(s12 + (long long)gw * NR);
    const float4* r2 = (const float4*)(s12 + (long long)SSZ + (long long)gw * NR);
    float4 v1[4], v2[4];
    float m1 = -1e30f, m2 = -1e30f;
    #pragma unroll
    for (int i = 0; i < 4; i++) {
        v1[i] = r1[lane + 32*i]; v2[i] = r2[lane + 32*i];
        m1 = fmaxf(m1, fmaxf(fmaxf(v1[i].x, v1[i].y), fmaxf(v1[i].z, v1[i].w)));
        m2 = fmaxf(m2, fmaxf(fmaxf(v2[i].x, v2[i].y), fmaxf(v2[i].z, v2[i].w)));
    }
    #pragma unroll
    for (int o = 16; o; o >>= 1) {
        m1 = fmaxf(m1, __shfl_xor_sync(0xffffffffu, m1, o));
        m2 = fmaxf(m2, __shfl_xor_sync(0xffffffffu, m2, o));
    }
    float a1 = 0.f, a2 = 0.f;
    #pragma unroll
    for (int i = 0; i < 4; i++) {
        v1[i].x = __expf(v1[i].x-m1); v1[i].y = __expf(v1[i].y-m1);
        v1[i].z = __expf(v1[i].z-m1); v1[i].w = __expf(v1[i].w-m1);
        v2[i].x = __expf(v2[i].x-m2); v2[i].y = __expf(v2[i].y-m2);
        v2[i].z = __expf(v2[i].z-m2); v2[i].w = __expf(v2[i].w-m2);
        a1 += v1[i].x+v1[i].y+v1[i].z+v1[i].w;
        a2 += v2[i].x+v2[i].y+v2[i].z+v2[i].w;
    }
    #pragma unroll
    for (int o = 16; o; o >>= 1) {
        a1 += __shfl_xor_sync(0xffffffffu, a1, o);
        a2 += __shfl_xor_sync(0xffffffffu, a2, o);
    }
    float is1 = 1.f/a1, is2 = lamp[0]/a2;
    #pragma unroll
    for (int i = 0; i < 4; i++) {
        float o0 = v1[i].x*is1 - v2[i].x*is2;
        float o1 = v1[i].y*is1 - v2[i].y*is2;
        float o2 = v1[i].z*is1 - v2[i].z*is2;
        float o3 = v1[i].w*is1 - v2[i].w*is2;
        ushort4 h, l;
        split1(o0,h.x,l.x); split1(o1,h.y,l.y); split1(o2,h.z,l.z); split1(o3,h.w,l.w);
        ph[(long long)gw*128 + lane + 32*i] = h;
        pl[(long long)gw*128 + lane + 32*i] = l;
    }
}

// upsample 512 -> 4096
__global__ void upsample_kernel(const float4* __restrict__ lr, float4* __restrict__ out)
{
    int idx = blockIdx.x*blockDim.x + threadIdx.x;
    if (idx >= NB*NL*NC/4) return;
    int c4 = idx & 255, j = (idx >> 8) & (NL-1), b = idx >> 20;
    float coords = fminf(fmaxf(((float)j + 0.5f)*0.125f - 0.5f, 0.f), 511.f);
    int lo = (int)coords;
    int hi = min(lo + 1, 511);
    float w = coords - (float)lo, w0 = 1.f - w;
    long long base = (long long)b * NR * 256;
    float4 a = lr[base + (long long)lo*256 + c4];
    float4 c = lr[base + (long long)hi*256 + c4];
    float4 o;
    o.x = a.x*w0 + c.x*w; o.y = a.y*w0 + c.y*w;
    o.z = a.z*w0 + c.z*w; o.w = a.w*w0 + c.w*w;
    out[idx] = o;
}

// ======================= host launcher =======================================
extern "C" void kernel_launch(void* const* d_in, const int* in_sizes, int n_in,
                              void* d_out, int out_size)
{
    const float* x   = (const float*)d_in[0];
    const float* Wq  = (const float*)d_in[1];
    const float* Wk  = (const float*)d_in[2];
    const float* Wv  = (const float*)d_in[3];
    const float* Wo  = (const float*)d_in[4];
    const float* qw  = (const float*)d_in[5];
    const float* kw  = (const float*)d_in[6];
    const float* hw  = (const float*)d_in[7];
    const float* lq1 = (const float*)d_in[8];
    const float* lk1 = (const float*)d_in[9];
    const float* lq2 = (const float*)d_in[10];
    const float* lk2 = (const float*)d_in[11];

    float* full_out = (float*)d_out;
    float* lowrank  = full_out + (size_t)NB*NL*NC;

    #define GS(p, s) cudaGetSymbolAddress((void**)&p, s)
    __nv_bfloat16 *xdh,*xdl,*Wh,*Wl,*Woh,*Wol;
    __nv_bfloat16 *q12h,*q12l,*k12h,*k12l,*vth,*vtl,*ph,*pl,*yh,*yl;
    float *qkv,*s12,*lam;
    GS(xdh,g_xdh); GS(xdl,g_xdl);
    GS(Wh,g_Wh); GS(Wl,g_Wl); GS(Woh,g_Woh); GS(Wol,g_Wol);
    GS(qkv,g_qkv);
    GS(q12h,g_q12h); GS(q12l,g_q12l); GS(k12h,g_k12h); GS(k12l,g_k12l);
    GS(vth,g_vth); GS(vtl,g_vtl);
    GS(s12,g_s12); GS(ph,g_ph); GS(pl,g_pl);
    GS(yh,g_yh); GS(yl,g_yl); GS(lam,g_lam);
    #undef GS

    cudaFuncSetAttribute(gemm_mma, cudaFuncAttributeMaxDynamicSharedMemorySize, GEMM_SMEM);

    // 1. downsample + split; weights split
    downsample_split<<<(NB*NR*NC/4 + 255)/256, 256>>>((const float4*)x, (ushort4*)xdh, (ushort4*)xdl);
    dim3 gcv((NC*NC/4 + 255)/256, 4);
    convert_split4<<<gcv, 256>>>((const float4*)Wq, (const float4*)Wk,
                                 (const float4*)Wv, (const float4*)Wo,
                                 (ushort4*)Wh, (ushort4*)Wl, (ushort4*)Woh, (ushort4*)Wol);

    // 2. QKV projections (one launch, z selects weight)
    dim3 gqkv(NC/128, (NB*NR)/128, 3);
    gemm_mma<<<gqkv, 256, GEMM_SMEM>>>(xdh, xdl, Wh, Wl, qkv, NB*NR, NC, NC,
        0, (long long)NC*NC, (long long)QKVSZ, 1.f, 0, nullptr, nullptr, nullptr);

    // 3. norm+rope+split, v transpose+split, lambda
    normrope_split<<<(2*NB*NR*NH*2*32 + 255)/256, 256>>>(qkv, qkv + QKVSZ, qw, kw,
        q12h, q12l, k12h, k12l);
    dim3 gvt(4, 16, 32), bvt(32, 8);
    vtrans_split<<<gvt, bvt>>>(qkv + 2*QKVSZ, vth, vtl);
    lambda_kernel<<<1, 32>>>(lq1, lk1, lq2, lk2, lam);

    // 4. both score GEMMs in one launch
    dim3 gsc(NR/128, NR/128, 2*NB*NH);
    gemm_mma<<<gsc, 256, GEMM_SMEM>>>(q12h, q12l, k12h, k12l, s12, NR, NR, ND,
        (long long)NR*ND, (long long)NR*ND, (long long)NR*NR, 0.125f, 0,
        nullptr, nullptr, nullptr);

    // 5. dual softmax + combine -> split probs
    softmax_combine<<<(NB*NH*NR*32 + 255)/256, 256>>>(s12, lam, (ushort4*)ph, (ushort4*)pl);

    // 6. PV GEMM with FUSED head rmsnorm -> yh/yl directly
    dim3 gpv(1, NR/128, NB*NH);
    gemm_mma<<<gpv, 256, GEMM_SMEM>>>(ph, pl, vth, vtl, nullptr, NR, 128, NR,
        (long long)NR*NR, (long long)128*NR, 0, 1.f, 2, hw, yh, yl);

    // 7. Wo projection + fused silu -> lowrank_out
    dim3 gwo(NC/128, (NB*NR)/128, 1);
    gemm_mma<<<gwo, 256, GEMM_SMEM>>>(yh, yl, Woh, Wol, lowrank, NB*NR, NC, NC,
        0, 0, 0, 1.f, 1, nullptr, nullptr, nullptr);

    // 8. upsample -> full_out
    upsample_kernel<<<(NB*NL*NC/4 + 255)/256, 256>>>((const float4*)lowrank, (float4*)full_out);
}

// round 7
// speedup vs baseline: 2.7751x; 1.0182x over previous
#include <cuda_runtime.h>
#include <cuda_bf16.h>
#include <math.h>
#include <stdint.h>

#define NB 4
#define NL 4096
#define NC 1024
#define NH 8
#define NR 512
#define ND 64
#define LAMBDA_INIT 0.8f
#define EPS 1e-6f

#define SZQ   (NB*NH*NR*ND)
#define SSZ   (NB*NH*NR*NR)

// ======================= device scratch (no allocs allowed) ==================
__device__ __nv_bfloat16 g_xdh[NB*NR*NC], g_xdl[NB*NR*NC];
__device__ __nv_bfloat16 g_Wh[3*NC*NC], g_Wl[3*NC*NC];
__device__ __nv_bfloat16 g_Woh[NC*NC], g_Wol[NC*NC];
__device__ __nv_bfloat16 g_q12h[2*SZQ], g_q12l[2*SZQ];
__device__ __nv_bfloat16 g_k12h[2*SZQ], g_k12l[2*SZQ];
__device__ __nv_bfloat16 g_vth[NB*NH*128*NR], g_vtl[NB*NH*128*NR];
__device__ float g_s12[2*SSZ];
__device__ __nv_bfloat16 g_ph[SSZ], g_pl[SSZ];
__device__ __nv_bfloat16 g_yh[NB*NR*NC], g_yl[NB*NR*NC];
__device__ float g_lam[1];

// ======================= asm helpers =========================================
__device__ __forceinline__ uint32_t smem_u32(const void* p){
    uint32_t a;
    asm("{ .reg .u64 t; cvta.to.shared.u64 t, %1; cvt.u32.u64 %0, t; }" : "=r"(a) : "l"(p));
    return a;
}
__device__ __forceinline__ void cpa16(uint32_t d, const void* s){
    asm volatile("cp.async.cg.shared.global [%0], [%1], 16;" :: "r"(d), "l"(s));
}
#define CP_COMMIT() asm volatile("cp.async.commit_group;" ::: "memory")
#define CP_WAIT0()  asm volatile("cp.async.wait_group 0;" ::: "memory")
#define CP_WAIT1()  asm volatile("cp.async.wait_group 1;" ::: "memory")

__device__ __forceinline__ void mma16816(float* c,
    uint32_t a0, uint32_t a1, uint32_t a2, uint32_t a3, uint32_t b0, uint32_t b1)
{
    asm volatile(
        "mma.sync.aligned.m16n8k16.row.col.f32.bf16.bf16.f32 "
        "{%0,%1,%2,%3}, {%4,%5,%6,%7}, {%8,%9}, {%0,%1,%2,%3};"
        : "+f"(c[0]), "+f"(c[1]), "+f"(c[2]), "+f"(c[3])
        : "r"(a0), "r"(a1), "r"(a2), "r"(a3), "r"(b0), "r"(b1));
}
#define LDSM4(r0,r1,r2,r3, addr) \
    asm volatile("ldmatrix.sync.aligned.m8n8.x4.shared.b16 {%0,%1,%2,%3}, [%4];" \
        : "=r"(r0),"=r"(r1),"=r"(r2),"=r"(r3) : "r"(addr))

__device__ __forceinline__ void split1(float v, unsigned short& h, unsigned short& l){
    __nv_bfloat16 hb = __float2bfloat16(v);
    __nv_bfloat16 lb = __float2bfloat16(v - __bfloat162float(hb));
    h = __bfloat16_as_ushort(hb); l = __bfloat16_as_ushort(lb);
}

// ======================= HMMA split-bf16 batched NT GEMM =====================
// mode 0: C = alpha*acc   1: silu   2: PV headnorm->yh/yl   3: QKV fused epilogue
#define ROW_B   80
#define TILE_B  (128*ROW_B)
#define STG_B   (4*TILE_B)
#define GEMM_SMEM (2*STG_B)          // 81920 -> 2 CTAs/SM

__device__ __forceinline__ void ld_stage(uint32_t sbase, int tid, long long c32,
    const __nv_bfloat16* Ahb, const __nv_bfloat16* Alb,
    const __nv_bfloat16* Bhb, const __nv_bfloat16* Blb, int K)
{
    int seg = tid & 3;
    #pragma unroll
    for (int it = 0; it < 8; it++) {
        int i = tid + it*256;
        int r = (i >> 2) & 127;
        const __nv_bfloat16* src =
            (it < 2) ? Ahb : (it < 4) ? Alb : (it < 6) ? Bhb : Blb;
        cpa16(sbase + (it >> 1)*TILE_B + r*ROW_B + seg*16,
              src + (long long)r*K + c32 + seg*8);
    }
    CP_COMMIT();
}

__global__ __launch_bounds__(256, 2)
void gemm_mma(const __nv_bfloat16* __restrict__ Ah, const __nv_bfloat16* __restrict__ Al,
              const __nv_bfloat16* __restrict__ Bh, const __nv_bfloat16* __restrict__ Bl,
              float* __restrict__ C, int M, int N, int K,
              long long sA, long long sB, long long sC, float alpha, int mode,
              const float* __restrict__ w1, const float* __restrict__ w2)
{
    extern __shared__ char sm[];
    uint32_t sb = smem_u32(sm);
    const int tid  = threadIdx.x;
    const int wid  = tid >> 5, lane = tid & 31;
    const int gid  = lane >> 2, tig = lane & 3;
    const int wm   = (wid & 1) * 64;
    const int wn   = (wid >> 1) * 32;
    const int bm   = blockIdx.y * 128, bn = blockIdx.x * 128;
    const int z    = blockIdx.z;

    const __nv_bfloat16* Ahb = Ah + z*sA + (long long)bm*K;
    const __nv_bfloat16* Alb = Al + z*sA + (long long)bm*K;
    const __nv_bfloat16* Bhb = Bh + z*sB + (long long)bn*K;
    const __nv_bfloat16* Blb = Bl + z*sB + (long long)bn*K;

    const int a_row = (lane & 7) + ((lane & 8)  ? 8 : 0);
    const int a_col = (lane & 16) ? 16 : 0;
    const int b_row = (lane & 7) + ((lane & 16) ? 8 : 0);
    const int b_col = (lane & 8)  ? 16 : 0;

    float acc[4][4][4];
    #pragma unroll
    for (int mi = 0; mi < 4; mi++)
        #pragma unroll
        for (int ni = 0; ni < 4; ni++)
            #pragma unroll
            for (int t = 0; t < 4; t++) acc[mi][ni][t] = 0.f;

    const int nch = K >> 5;
    ld_stage(sb, tid, 0, Ahb, Alb, Bhb, Blb, K);

    for (int c = 0; c < nch; c++) {
        if (c + 1 < nch) {
            ld_stage(sb + ((c + 1) & 1)*STG_B, tid, (long long)(c + 1)*32,
                     Ahb, Alb, Bhb, Blb, K);
            CP_WAIT1();
        } else {
            CP_WAIT0();
        }
        __syncthreads();

        const uint32_t p = sb + (c & 1)*STG_B;
        const uint32_t pAh = p,            pAl = p +   TILE_B;
        const uint32_t pBh = p + 2*TILE_B, pBl = p + 3*TILE_B;

        #pragma unroll
        for (int kk = 0; kk < 2; kk++) {
            const int ko = kk*32;
            uint32_t bh[4][2], bl[4][2];
            #pragma unroll
            for (int nj = 0; nj < 2; nj++) {
                uint32_t bd = pBh + (wn + nj*16 + b_row)*ROW_B + ko + b_col;
                LDSM4(bh[2*nj][0], bh[2*nj][1], bh[2*nj+1][0], bh[2*nj+1][1], bd);
                uint32_t bd2 = pBl + (wn + nj*16 + b_row)*ROW_B + ko + b_col;
                LDSM4(bl[2*nj][0], bl[2*nj][1], bl[2*nj+1][0], bl[2*nj+1][1], bd2);
            }
            #pragma unroll
            for (int mi = 0; mi < 4; mi++) {
                uint32_t ah[4], al[4];
                uint32_t ad  = pAh + (wm + mi*16 + a_row)*ROW_B + ko + a_col;
                LDSM4(ah[0], ah[1], ah[2], ah[3], ad);
                uint32_t ad2 = pAl + (wm + mi*16 + a_row)*ROW_B + ko + a_col;
                LDSM4(al[0], al[1], al[2], al[3], ad2);
                #pragma unroll
                for (int ni = 0; ni < 4; ni++) {
                    mma16816(acc[mi][ni], ah[0], ah[1], ah[2], ah[3], bh[ni][0], bh[ni][1]);
                    mma16816(acc[mi][ni], al[0], al[1], al[2], al[3], bh[ni][0], bh[ni][1]);
                    mma16816(acc[mi][ni], ah[0], ah[1], ah[2], ah[3], bl[ni][0], bl[ni][1]);
                }
            }
        }
        __syncthreads();
    }

    if (mode == 0 || mode == 1) {
        float* Cb = C + z*sC;
        #pragma unroll
        for (int mi = 0; mi < 4; mi++) {
            #pragma unroll
            for (int ni = 0; ni < 4; ni++) {
                int row = bm + wm + mi*16 + gid;
                int col = bn + wn + ni*8 + tig*2;
                float v0 = acc[mi][ni][0]*alpha, v1 = acc[mi][ni][1]*alpha;
                float v2 = acc[mi][ni][2]*alpha, v3 = acc[mi][ni][3]*alpha;
                if (mode == 1) {
                    v0 /= (1.f + __expf(-v0)); v1 /= (1.f + __expf(-v1));
                    v2 /= (1.f + __expf(-v2)); v3 /= (1.f + __expf(-v3));
                }
                *(float2*)&Cb[(long long)row*N + col]       = make_float2(v0, v1);
                *(float2*)&Cb[(long long)(row + 8)*N + col] = make_float2(v2, v3);
            }
        }
        return;
    }

    // ---------- stage accumulators to smem (row-major, or transposed for v) ---
    float* esm = (float*)sm;   // 128 x 132 floats
    const bool vtr = (mode == 3 && z == 2);
    #pragma unroll
    for (int mi = 0; mi < 4; mi++) {
        #pragma unroll
        for (int ni = 0; ni < 4; ni++) {
            int r0 = wm + mi*16 + gid;
            int cc = wn + ni*8 + tig*2;
            if (vtr) {
                esm[cc*132 + r0]         = acc[mi][ni][0];
                esm[(cc+1)*132 + r0]     = acc[mi][ni][1];
                esm[cc*132 + r0 + 8]     = acc[mi][ni][2];
                esm[(cc+1)*132 + r0 + 8] = acc[mi][ni][3];
            } else {
                esm[r0*132 + cc]         = acc[mi][ni][0];
                esm[r0*132 + cc + 1]     = acc[mi][ni][1];
                esm[(r0+8)*132 + cc]     = acc[mi][ni][2];
                esm[(r0+8)*132 + cc + 1] = acc[mi][ni][3];
            }
        }
    }
    __syncthreads();

    if (mode == 2) {
        // fused head rmsnorm (PV): z = b*8+h
        const int b = z >> 3, h = z & 7;
        for (int r = wid; r < 128; r += 8) {
            float4 vv = *(float4*)&esm[r*132 + lane*4];
            float ssq = vv.x*vv.x + vv.y*vv.y + vv.z*vv.z + vv.w*vv.w;
            #pragma unroll
            for (int o = 16; o; o >>= 1) ssq += __shfl_xor_sync(0xffffffffu, ssq, o);
            float inv = (1.f - LAMBDA_INIT) * rsqrtf(ssq*(1.f/128.f) + EPS);
            float4 w = ((const float4*)w1)[lane];
            float o0 = vv.x*inv*w.x, o1 = vv.y*inv*w.y, o2 = vv.z*inv*w.z, o3 = vv.w*inv*w.w;
            ushort4 hh, ll;
            split1(o0,hh.x,ll.x); split1(o1,hh.y,ll.y); split1(o2,hh.z,ll.z); split1(o3,hh.w,ll.w);
            int i = bm + r;
            long long o4 = (long long)(b*NR + i)*256 + h*32 + lane;
            ((ushort4*)g_yh)[o4] = hh;
            ((ushort4*)g_yl)[o4] = ll;
        }
        return;
    }

    // ---------- mode 3: fused QKV epilogue ------------------------------------
    const int h = blockIdx.x;          // head index (tile cols = one head)
    if (z < 2) {
        // rmsnorm(64) + rope(pos=h) + split -> q12 / k12
        const float* w = z ? w2 : w1;
        const int gidx = lane & 15, sgi = lane >> 4;
        const int dmb = (gidx & 7) * 4;
        float4 wv = ((const float4*)w)[gidx];
        float sn[4], cs[4];
        #pragma unroll
        for (int j = 0; j < 4; j++) {
            float f = exp2f(-0.41524101186351494f * (float)(dmb + j));
            __sincosf((float)h * f, &sn[j], &cs[j]);
        }
        __nv_bfloat16* dh = (z == 0 ? g_q12h : g_k12h) + (long long)sgi*SZQ;
        __nv_bfloat16* dl = (z == 0 ? g_q12l : g_k12l) + (long long)sgi*SZQ;
        const bool lo = (gidx & 8) == 0;
        for (int r = wid; r < 128; r += 8) {
            float4 xv = *(float4*)&esm[r*132 + sgi*64 + gidx*4];
            float ssq = xv.x*xv.x + xv.y*xv.y + xv.z*xv.z + xv.w*xv.w;
            #pragma unroll
            for (int o = 8; o; o >>= 1) ssq += __shfl_xor_sync(0xffffffffu, ssq, o);
            float inv = rsqrtf(ssq*(1.f/64.f) + EPS);
            float n0 = xv.x*inv*wv.x, n1 = xv.y*inv*wv.y;
            float n2 = xv.z*inv*wv.z, n3 = xv.w*inv*wv.w;
            float p0 = __shfl_xor_sync(0xffffffffu, n0, 8);
            float p1 = __shfl_xor_sync(0xffffffffu, n1, 8);
            float p2 = __shfl_xor_sync(0xffffffffu, n2, 8);
            float p3 = __shfl_xor_sync(0xffffffffu, n3, 8);
            float o0 = lo ? n0*cs[0] - p0*sn[0] : p0*sn[0] + n0*cs[0];
            float o1 = lo ? n1*cs[1] - p1*sn[1] : p1*sn[1] + n1*cs[1];
            float o2 = lo ? n2*cs[2] - p2*sn[2] : p2*sn[2] + n2*cs[2];
            float o3 = lo ? n3*cs[3] - p3*sn[3] : p3*sn[3] + n3*cs[3];
            ushort4 hh, ll;
            split1(o0,hh.x,ll.x); split1(o1,hh.y,ll.y); split1(o2,hh.z,ll.z); split1(o3,hh.w,ll.w);
            int tok = bm + r, b = tok >> 9, il = tok & 511;
            long long off = ((long long)((b*NH + h)*NR) + il)*64 + gidx*4;
            *(ushort4*)(dh + off) = hh;
            *(ushort4*)(dl + off) = ll;
        }
    } else {
        // v: transposed split write -> vth/vtl  (esm staged transposed)
        const int b = bm >> 9, ibase = bm & 511;
        const int bh = b*NH + h;
        #pragma unroll
        for (int it = 0; it < 32; it++) {
            int e = tid + it*256;
            int c = e >> 6, ip = e & 63, i = ip*2;
            float2 vv = *(float2*)&esm[c*132 + i];
            unsigned short h0, l0, h1, l1;
            split1(vv.x, h0, l0); split1(vv.y, h1, l1);
            long long o = ((long long)(bh*128 + c))*NR + ibase + i;
            *(ushort2*)(g_vth + o) = make_ushort2(h0, h1);
            *(ushort2*)(g_vtl + o) = make_ushort2(l0, l1);
        }
    }
}

// ======================= elementwise kernels =================================
__global__ void downsample_split(const float4* __restrict__ x,
                                 ushort4* __restrict__ xh, ushort4* __restrict__ xl)
{
    int idx = blockIdx.x*blockDim.x + threadIdx.x;
    if (idx >= NB*NR*NC/4) return;
    int c4 = idx & 255, bi = idx >> 8;
    int i = bi & (NR-1), b = bi >> 9;
    long long row = (long long)b*NL + 8*i + 3;
    float4 p = x[row*256 + c4], q = x[(row+1)*256 + c4];
    float v0 = 0.5f*(p.x+q.x), v1 = 0.5f*(p.y+q.y), v2 = 0.5f*(p.z+q.z), v3 = 0.5f*(p.w+q.w);
    ushort4 h, l;
    split1(v0, h.x, l.x); split1(v1, h.y, l.y); split1(v2, h.z, l.z); split1(v3, h.w, l.w);
    xh[idx] = h; xl[idx] = l;
}

__global__ void convert_split4(const float4* __restrict__ Wq, const float4* __restrict__ Wk,
                               const float4* __restrict__ Wv, const float4* __restrict__ Wo,
                               ushort4* __restrict__ wh, ushort4* __restrict__ wl,
                               ushort4* __restrict__ oh, ushort4* __restrict__ ol)
{
    int idx = blockIdx.x*blockDim.x + threadIdx.x;
    if (idx >= NC*NC/4) return;
    const float4* s; ushort4 *dh, *dl; int off = 0;
    switch (blockIdx.y) {
        case 0: s = Wq; dh = wh; dl = wl; off = 0;          break;
        case 1: s = Wk; dh = wh; dl = wl; off = NC*NC/4;    break;
        case 2: s = Wv; dh = wh; dl = wl; off = 2*(NC*NC/4);break;
        default:s = Wo; dh = oh; dl = ol; off = 0;          break;
    }
    float4 v = s[idx];
    ushort4 h, l;
    split1(v.x, h.x, l.x); split1(v.y, h.y, l.y); split1(v.z, h.z, l.z); split1(v.w, h.w, l.w);
    dh[off + idx] = h; dl[off + idx] = l;
}

__global__ void lambda_kernel(const float* lq1, const float* lk1,
                              const float* lq2, const float* lk2, float* out)
{
    int t = threadIdx.x;
    float a = lq1[t]*lk1[t] + lq1[t+32]*lk1[t+32];
    float b = lq2[t]*lk2[t] + lq2[t+32]*lk2[t+32];
    #pragma unroll
    for (int o = 16; o; o >>= 1) {
        a += __shfl_xor_sync(0xffffffffu, a, o);
        b += __shfl_xor_sync(0xffffffffu, b, o);
    }
    if (t == 0) out[0] = expf(a) - expf(b) + LAMBDA_INIT;
}

// dual softmax + combine -> split bf16 probs
__global__ void softmax_combine(const float* __restrict__ s12,
                                const float* __restrict__ lamp,
                                ushort4* __restrict__ ph, ushort4* __restrict__ pl)
{
    int gw   = (blockIdx.x*blockDim.x + threadIdx.x) >> 5;
    int lane = threadIdx.x & 31;
    if (gw >= NB*NH*NR) return;
    const float4* r1 = (const float4*)(s12 + (long long)gw * NR);
    const float4* r2 = (const float4*)(s12 + (long long)SSZ + (long long)gw * NR);
    float4 v1[4], v2[4];
    float m1 = -1e30f, m2 = -1e30f;
    #pragma unroll
    for (int i = 0; i < 4; i++) {
        v1[i] = r1[lane + 32*i]; v2[i] = r2[lane + 32*i];
        m1 = fmaxf(m1, fmaxf(fmaxf(v1[i].x, v1[i].y), fmaxf(v1[i].z, v1[i].w)));
        m2 = fmaxf(m2, fmaxf(fmaxf(v2[i].x, v2[i].y), fmaxf(v2[i].z, v2[i].w)));
    }
    #pragma unroll
    for (int o = 16; o; o >>= 1) {
        m1 = fmaxf(m1, __shfl_xor_sync(0xffffffffu, m1, o));
        m2 = fmaxf(m2, __shfl_xor_sync(0xffffffffu, m2, o));
    }
    float a1 = 0.f, a2 = 0.f;
    #pragma unroll
    for (int i = 0; i < 4; i++) {
        v1[i].x = __expf(v1[i].x-m1); v1[i].y = __expf(v1[i].y-m1);
        v1[i].z = __expf(v1[i].z-m1); v1[i].w = __expf(v1[i].w-m1);
        v2[i].x = __expf(v2[i].x-m2); v2[i].y = __expf(v2[i].y-m2);
        v2[i].z = __expf(v2[i].z-m2); v2[i].w = __expf(v2[i].w-m2);
        a1 += v1[i].x+v1[i].y+v1[i].z+v1[i].w;
        a2 += v2[i].x+v2[i].y+v2[i].z+v2[i].w;
    }
    #pragma unroll
    for (int o = 16; o; o >>= 1) {
        a1 += __shfl_xor_sync(0xffffffffu, a1, o);
        a2 += __shfl_xor_sync(0xffffffffu, a2, o);
    }
    float is1 = 1.f/a1, is2 = lamp[0]/a2;
    #pragma unroll
    for (int i = 0; i < 4; i++) {
        float o0 = v1[i].x*is1 - v2[i].x*is2;
        float o1 = v1[i].y*is1 - v2[i].y*is2;
        float o2 = v1[i].z*is1 - v2[i].z*is2;
        float o3 = v1[i].w*is1 - v2[i].w*is2;
        ushort4 h, l;
        split1(o0,h.x,l.x); split1(o1,h.y,l.y); split1(o2,h.z,l.z); split1(o3,h.w,l.w);
        ph[(long long)gw*128 + lane + 32*i] = h;
        pl[(long long)gw*128 + lane + 32*i] = l;
    }
}

// upsample 512 -> 4096
__global__ void upsample_kernel(const float4* __restrict__ lr, float4* __restrict__ out)
{
    int idx = blockIdx.x*blockDim.x + threadIdx.x;
    if (idx >= NB*NL*NC/4) return;
    int c4 = idx & 255, j = (idx >> 8) & (NL-1), b = idx >> 20;
    float coords = fminf(fmaxf(((float)j + 0.5f)*0.125f - 0.5f, 0.f), 511.f);
    int lo = (int)coords;
    int hi = min(lo + 1, 511);
    float w = coords - (float)lo, w0 = 1.f - w;
    long long base = (long long)b * NR * 256;
    float4 a = lr[base + (long long)lo*256 + c4];
    float4 c = lr[base + (long long)hi*256 + c4];
    float4 o;
    o.x = a.x*w0 + c.x*w; o.y = a.y*w0 + c.y*w;
    o.z = a.z*w0 + c.z*w; o.w = a.w*w0 + c.w*w;
    out[idx] = o;
}

// ======================= host launcher =======================================
extern "C" void kernel_launch(void* const* d_in, const int* in_sizes, int n_in,
                              void* d_out, int out_size)
{
    const float* x   = (const float*)d_in[0];
    const float* Wq  = (const float*)d_in[1];
    const float* Wk  = (const float*)d_in[2];
    const float* Wv  = (const float*)d_in[3];
    const float* Wo  = (const float*)d_in[4];
    const float* qw  = (const float*)d_in[5];
    const float* kw  = (const float*)d_in[6];
    const float* hw  = (const float*)d_in[7];
    const float* lq1 = (const float*)d_in[8];
    const float* lk1 = (const float*)d_in[9];
    const float* lq2 = (const float*)d_in[10];
    const float* lk2 = (const float*)d_in[11];

    float* full_out = (float*)d_out;
    float* lowrank  = full_out + (size_t)NB*NL*NC;

    #define GS(p, s) cudaGetSymbolAddress((void**)&p, s)
    __nv_bfloat16 *xdh,*xdl,*Wh,*Wl,*Woh,*Wol;
    __nv_bfloat16 *q12h,*q12l,*k12h,*k12l,*vth,*vtl,*ph,*pl,*yh,*yl;
    float *s12,*lam;
    GS(xdh,g_xdh); GS(xdl,g_xdl);
    GS(Wh,g_Wh); GS(Wl,g_Wl); GS(Woh,g_Woh); GS(Wol,g_Wol);
    GS(q12h,g_q12h); GS(q12l,g_q12l); GS(k12h,g_k12h); GS(k12l,g_k12l);
    GS(vth,g_vth); GS(vtl,g_vtl);
    GS(s12,g_s12); GS(ph,g_ph); GS(pl,g_pl);
    GS(yh,g_yh); GS(yl,g_yl); GS(lam,g_lam);
    #undef GS

    cudaFuncSetAttribute(gemm_mma, cudaFuncAttributeMaxDynamicSharedMemorySize, GEMM_SMEM);

    // 1. downsample + split; weights split; lambda
    downsample_split<<<(NB*NR*NC/4 + 255)/256, 256>>>((const float4*)x, (ushort4*)xdh, (ushort4*)xdl);
    dim3 gcv((NC*NC/4 + 255)/256, 4);
    convert_split4<<<gcv, 256>>>((const float4*)Wq, (const float4*)Wk,
                                 (const float4*)Wv, (const float4*)Wo,
                                 (ushort4*)Wh, (ushort4*)Wl, (ushort4*)Woh, (ushort4*)Wol);
    lambda_kernel<<<1, 32>>>(lq1, lk1, lq2, lk2, lam);

    // 2. QKV projections with FUSED normrope (z<2) / v-transpose (z=2) epilogues
    dim3 gqkv(NC/128, (NB*NR)/128, 3);
    gemm_mma<<<gqkv, 256, GEMM_SMEM>>>(xdh, xdl, Wh, Wl, nullptr, NB*NR, NC, NC,
        0, (long long)NC*NC, 0, 1.f, 3, qw, kw);

    // 3. both score GEMMs in one launch (z in [0,64) spans s1|s2)
    dim3 gsc(NR/128, NR/128, 2*NB*NH);
    gemm_mma<<<gsc, 256, GEMM_SMEM>>>(q12h, q12l, k12h, k12l, s12, NR, NR, ND,
        (long long)NR*ND, (long long)NR*ND, (long long)NR*NR, 0.125f, 0, nullptr, nullptr);

    // 4. dual softmax + combine -> split probs
    softmax_combine<<<(NB*NH*NR*32 + 255)/256, 256>>>(s12, lam, (ushort4*)ph, (ushort4*)pl);

    // 5. PV GEMM with FUSED head rmsnorm -> yh/yl
    dim3 gpv(1, NR/128, NB*NH);
    gemm_mma<<<gpv, 256, GEMM_SMEM>>>(ph, pl, vth, vtl, nullptr, NR, 128, NR,
        (long long)NR*NR, (long long)128*NR, 0, 1.f, 2, hw, nullptr);

    // 6. Wo projection + fused silu -> lowrank_out
    dim3 gwo(NC/128, (NB*NR)/128, 1);
    gemm_mma<<<gwo, 256, GEMM_SMEM>>>(yh, yl, Woh, Wol, lowrank, NB*NR, NC, NC,
        0, 0, 0, 1.f, 1, nullptr, nullptr);

    // 7. upsample -> full_out
    upsample_kernel<<<(NB*NL*NC/4 + 255)/256, 256>>>((const float4*)lowrank, (float4*)full_out);
}

// round 8
// speedup vs baseline: 4.6189x; 1.6644x over previous
#include <cuda_runtime.h>
#include <cuda_fp16.h>
#include <math.h>
#include <stdint.h>

#define NB 4
#define NL 4096
#define NC 1024
#define NH 8
#define NR 512
#define ND 64
#define LAMBDA_INIT 0.8f
#define EPS 1e-6f

#define SZQ   (NB*NH*NR*ND)
#define SSZ   (NB*NH*NR*NR)

// ======================= device scratch (no allocs allowed) ==================
__device__ __half g_xd [NB*NR*NC];
__device__ __half g_W  [3*NC*NC];          // Wq,Wk,Wv
__device__ __half g_Wo [NC*NC];
__device__ __half g_q12[2*SZQ];
__device__ __half g_k12[2*SZQ];
__device__ __half g_vt [NB*NH*128*NR];
__device__ float  g_s12[2*SSZ];
__device__ __half g_p  [SSZ];
__device__ __half g_y  [NB*NR*NC];
__device__ float  g_lam[1];

// ======================= asm helpers =========================================
__device__ __forceinline__ uint32_t smem_u32(const void* p){
    uint32_t a;
    asm("{ .reg .u64 t; cvta.to.shared.u64 t, %1; cvt.u32.u64 %0, t; }" : "=r"(a) : "l"(p));
    return a;
}
__device__ __forceinline__ void cpa16(uint32_t d, const void* s){
    asm volatile("cp.async.cg.shared.global [%0], [%1], 16;" :: "r"(d), "l"(s));
}
#define CP_COMMIT() asm volatile("cp.async.commit_group;" ::: "memory")
#define CP_WAIT0()  asm volatile("cp.async.wait_group 0;" ::: "memory")
#define CP_WAIT1()  asm volatile("cp.async.wait_group 1;" ::: "memory")
#define CP_WAIT2()  asm volatile("cp.async.wait_group 2;" ::: "memory")

__device__ __forceinline__ void mma16816(float* c,
    uint32_t a0, uint32_t a1, uint32_t a2, uint32_t a3, uint32_t b0, uint32_t b1)
{
    asm volatile(
        "mma.sync.aligned.m16n8k16.row.col.f32.f16.f16.f32 "
        "{%0,%1,%2,%3}, {%4,%5,%6,%7}, {%8,%9}, {%0,%1,%2,%3};"
        : "+f"(c[0]), "+f"(c[1]), "+f"(c[2]), "+f"(c[3])
        : "r"(a0), "r"(a1), "r"(a2), "r"(a3), "r"(b0), "r"(b1));
}
#define LDSM4(r0,r1,r2,r3, addr) \
    asm volatile("ldmatrix.sync.aligned.m8n8.x4.shared.b16 {%0,%1,%2,%3}, [%4];" \
        : "=r"(r0),"=r"(r1),"=r"(r2),"=r"(r3) : "r"(addr))

__device__ __forceinline__ unsigned short h1(float v){
    return __half_as_ushort(__float2half_rn(v));
}

// ======================= HMMA fp16 batched NT GEMM ===========================
// mode 0: C = alpha*acc   1: silu   2: PV headnorm->g_y   3: QKV fused epilogue
#define ROW_B   80
#define TILE_B  (128*ROW_B)          // 10240
#define STG_B   (2*TILE_B)           // A+B = 20480
#define GEMM_SMEM (4*STG_B)          // 81920 -> 2 CTAs/SM, 4-stage pipeline

__device__ __forceinline__ void ld_stage(uint32_t sbase, int tid, long long c32,
    const __half* Ab, const __half* Bb, int K)
{
    int seg = tid & 3;
    #pragma unroll
    for (int it = 0; it < 4; it++) {
        int i = tid + it*256;
        int r = (i >> 2) & 127;
        const __half* src = (it < 2) ? Ab : Bb;
        cpa16(sbase + (it >> 1)*TILE_B + r*ROW_B + seg*16,
              src + (long long)r*K + c32 + seg*8);
    }
    CP_COMMIT();
}

__global__ __launch_bounds__(256, 2)
void gemm_mma(const __half* __restrict__ A, const __half* __restrict__ B,
              float* __restrict__ C, int M, int N, int K,
              long long sA, long long sB, long long sC, float alpha, int mode,
              const float* __restrict__ w1, const float* __restrict__ w2)
{
    extern __shared__ char sm[];
    uint32_t sb = smem_u32(sm);
    const int tid  = threadIdx.x;
    const int wid  = tid >> 5, lane = tid & 31;
    const int gid  = lane >> 2, tig = lane & 3;
    const int wm   = (wid & 1) * 64;
    const int wn   = (wid >> 1) * 32;
    const int bm   = blockIdx.y * 128, bn = blockIdx.x * 128;
    const int z    = blockIdx.z;

    const __half* Ab = A + z*sA + (long long)bm*K;
    const __half* Bb = B + z*sB + (long long)bn*K;

    const int a_row = (lane & 7) + ((lane & 8)  ? 8 : 0);
    const int a_col = (lane & 16) ? 16 : 0;
    const int b_row = (lane & 7) + ((lane & 16) ? 8 : 0);
    const int b_col = (lane & 8)  ? 16 : 0;

    float acc[4][4][4];
    #pragma unroll
    for (int mi = 0; mi < 4; mi++)
        #pragma unroll
        for (int ni = 0; ni < 4; ni++)
            #pragma unroll
            for (int t = 0; t < 4; t++) acc[mi][ni][t] = 0.f;

    const int nch = K >> 5;
    ld_stage(sb, tid, 0, Ab, Bb, K);
    if (nch > 1) ld_stage(sb + STG_B,   tid, 32, Ab, Bb, K);
    if (nch > 2) ld_stage(sb + 2*STG_B, tid, 64, Ab, Bb, K);

    for (int c = 0; c < nch; c++) {
        if (c < nch - 2)      { CP_WAIT2(); }
        else if (c == nch - 2){ CP_WAIT1(); }
        else                  { CP_WAIT0(); }
        __syncthreads();                       // stage c ready; c-1 fully consumed
        if (c + 3 < nch)
            ld_stage(sb + ((c + 3) & 3)*STG_B, tid, (long long)(c + 3)*32, Ab, Bb, K);

        const uint32_t p  = sb + (c & 3)*STG_B;
        const uint32_t pA = p, pB = p + TILE_B;

        #pragma unroll
        for (int kk = 0; kk < 2; kk++) {
            const int ko = kk*32;
            uint32_t bh[4][2];
            #pragma unroll
            for (int nj = 0; nj < 2; nj++) {
                uint32_t bd = pB + (wn + nj*16 + b_row)*ROW_B + ko + b_col;
                LDSM4(bh[2*nj][0], bh[2*nj][1], bh[2*nj+1][0], bh[2*nj+1][1], bd);
            }
            #pragma unroll
            for (int mi = 0; mi < 4; mi++) {
                uint32_t ah[4];
                uint32_t ad = pA + (wm + mi*16 + a_row)*ROW_B + ko + a_col;
                LDSM4(ah[0], ah[1], ah[2], ah[3], ad);
                #pragma unroll
                for (int ni = 0; ni < 4; ni++)
                    mma16816(acc[mi][ni], ah[0], ah[1], ah[2], ah[3],
                             bh[ni][0], bh[ni][1]);
            }
        }
    }

    if (mode == 0 || mode == 1) {
        float* Cb = C + z*sC;
        #pragma unroll
        for (int mi = 0; mi < 4; mi++) {
            #pragma unroll
            for (int ni = 0; ni < 4; ni++) {
                int row = bm + wm + mi*16 + gid;
                int col = bn + wn + ni*8 + tig*2;
                float v0 = acc[mi][ni][0]*alpha, v1 = acc[mi][ni][1]*alpha;
                float v2 = acc[mi][ni][2]*alpha, v3 = acc[mi][ni][3]*alpha;
                if (mode == 1) {
                    v0 /= (1.f + __expf(-v0)); v1 /= (1.f + __expf(-v1));
                    v2 /= (1.f + __expf(-v2)); v3 /= (1.f + __expf(-v3));
                }
                *(float2*)&Cb[(long long)row*N + col]       = make_float2(v0, v1);
                *(float2*)&Cb[(long long)(row + 8)*N + col] = make_float2(v2, v3);
            }
        }
        return;
    }

    // ---------- stage accumulators to smem (row-major, or transposed for v) ---
    __syncthreads();                            // mainloop smem reads done
    float* esm = (float*)sm;                    // 128 x 132 floats
    const bool vtr = (mode == 3 && z == 2);
    #pragma unroll
    for (int mi = 0; mi < 4; mi++) {
        #pragma unroll
        for (int ni = 0; ni < 4; ni++) {
            int r0 = wm + mi*16 + gid;
            int cc = wn + ni*8 + tig*2;
            if (vtr) {
                esm[cc*132 + r0]         = acc[mi][ni][0];
                esm[(cc+1)*132 + r0]     = acc[mi][ni][1];
                esm[cc*132 + r0 + 8]     = acc[mi][ni][2];
                esm[(cc+1)*132 + r0 + 8] = acc[mi][ni][3];
            } else {
                esm[r0*132 + cc]         = acc[mi][ni][0];
                esm[r0*132 + cc + 1]     = acc[mi][ni][1];
                esm[(r0+8)*132 + cc]     = acc[mi][ni][2];
                esm[(r0+8)*132 + cc + 1] = acc[mi][ni][3];
            }
        }
    }
    __syncthreads();

    if (mode == 2) {
        // fused head rmsnorm (PV): z = b*8+h
        const int b = z >> 3, h = z & 7;
        for (int r = wid; r < 128; r += 8) {
            float4 vv = *(float4*)&esm[r*132 + lane*4];
            float ssq = vv.x*vv.x + vv.y*vv.y + vv.z*vv.z + vv.w*vv.w;
            #pragma unroll
            for (int o = 16; o; o >>= 1) ssq += __shfl_xor_sync(0xffffffffu, ssq, o);
            float inv = (1.f - LAMBDA_INIT) * rsqrtf(ssq*(1.f/128.f) + EPS);
            float4 w = ((const float4*)w1)[lane];
            ushort4 hh;
            hh.x = h1(vv.x*inv*w.x); hh.y = h1(vv.y*inv*w.y);
            hh.z = h1(vv.z*inv*w.z); hh.w = h1(vv.w*inv*w.w);
            int i = bm + r;
            long long o4 = (long long)(b*NR + i)*256 + h*32 + lane;
            ((ushort4*)g_y)[o4] = hh;
        }
        return;
    }

    // ---------- mode 3: fused QKV epilogue ------------------------------------
    const int h = blockIdx.x;              // tile cols = one head
    if (z < 2) {
        // rmsnorm(64) + rope(pos=h) + fp16 -> q12 / k12
        const float* w = z ? w2 : w1;
        const int gidx = lane & 15, sgi = lane >> 4;
        const int dmb = (gidx & 7) * 4;
        float4 wv = ((const float4*)w)[gidx];
        float sn[4], cs[4];
        #pragma unroll
        for (int j = 0; j < 4; j++) {
            float f = exp2f(-0.41524101186351494f * (float)(dmb + j));
            __sincosf((float)h * f, &sn[j], &cs[j]);
        }
        __half* dh = (z == 0 ? g_q12 : g_k12) + (long long)sgi*SZQ;
        const bool lo = (gidx & 8) == 0;
        for (int r = wid; r < 128; r += 8) {
            float4 xv = *(float4*)&esm[r*132 + sgi*64 + gidx*4];
            float ssq = xv.x*xv.x + xv.y*xv.y + xv.z*xv.z + xv.w*xv.w;
            #pragma unroll
            for (int o = 8; o; o >>= 1) ssq += __shfl_xor_sync(0xffffffffu, ssq, o);
            float inv = rsqrtf(ssq*(1.f/64.f) + EPS);
            float n0 = xv.x*inv*wv.x, n1 = xv.y*inv*wv.y;
            float n2 = xv.z*inv*wv.z, n3 = xv.w*inv*wv.w;
            float p0 = __shfl_xor_sync(0xffffffffu, n0, 8);
            float p1 = __shfl_xor_sync(0xffffffffu, n1, 8);
            float p2 = __shfl_xor_sync(0xffffffffu, n2, 8);
            float p3 = __shfl_xor_sync(0xffffffffu, n3, 8);
            ushort4 hh;
            hh.x = h1(lo ? n0*cs[0] - p0*sn[0] : p0*sn[0] + n0*cs[0]);
            hh.y = h1(lo ? n1*cs[1] - p1*sn[1] : p1*sn[1] + n1*cs[1]);
            hh.z = h1(lo ? n2*cs[2] - p2*sn[2] : p2*sn[2] + n2*cs[2]);
            hh.w = h1(lo ? n3*cs[3] - p3*sn[3] : p3*sn[3] + n3*cs[3]);
            int tok = bm + r, b = tok >> 9, il = tok & 511;
            long long off = ((long long)((b*NH + h)*NR) + il)*64 + gidx*4;
            *(ushort4*)(dh + off) = hh;
        }
    } else {
        // v: transposed fp16 write -> g_vt  (esm staged transposed)
        const int b = bm >> 9, ibase = bm & 511;
        const int bh = b*NH + h;
        #pragma unroll
        for (int it = 0; it < 32; it++) {
            int e = tid + it*256;
            int c = e >> 6, ip = e & 63, i = ip*2;
            float2 vv = *(float2*)&esm[c*132 + i];
            long long o = ((long long)(bh*128 + c))*NR + ibase + i;
            *(ushort2*)(g_vt + o) = make_ushort2(h1(vv.x), h1(vv.y));
        }
    }
}

// ======================= elementwise kernels =================================
__global__ void downsample_h(const float4* __restrict__ x, ushort4* __restrict__ xd)
{
    int idx = blockIdx.x*blockDim.x + threadIdx.x;
    if (idx >= NB*NR*NC/4) return;
    int c4 = idx & 255, bi = idx >> 8;
    int i = bi & (NR-1), b = bi >> 9;
    long long row = (long long)b*NL + 8*i + 3;
    float4 p = x[row*256 + c4], q = x[(row+1)*256 + c4];
    ushort4 h;
    h.x = h1(0.5f*(p.x+q.x)); h.y = h1(0.5f*(p.y+q.y));
    h.z = h1(0.5f*(p.z+q.z)); h.w = h1(0.5f*(p.w+q.w));
    xd[idx] = h;
}

__global__ void convert4(const float4* __restrict__ Wq, const float4* __restrict__ Wk,
                         const float4* __restrict__ Wv, const float4* __restrict__ Wo,
                         ushort4* __restrict__ w3, ushort4* __restrict__ wo)
{
    int idx = blockIdx.x*blockDim.x + threadIdx.x;
    if (idx >= NC*NC/4) return;
    const float4* s; ushort4* d; int off = 0;
    switch (blockIdx.y) {
        case 0: s = Wq; d = w3; off = 0;          break;
        case 1: s = Wk; d = w3; off = NC*NC/4;    break;
        case 2: s = Wv; d = w3; off = 2*(NC*NC/4);break;
        default:s = Wo; d = wo; off = 0;          break;
    }
    float4 v = s[idx];
    ushort4 h;
    h.x = h1(v.x); h.y = h1(v.y); h.z = h1(v.z); h.w = h1(v.w);
    d[off + idx] = h;
}

__global__ void lambda_kernel(const float* lq1, const float* lk1,
                              const float* lq2, const float* lk2, float* out)
{
    int t = threadIdx.x;
    float a = lq1[t]*lk1[t] + lq1[t+32]*lk1[t+32];
    float b = lq2[t]*lk2[t] + lq2[t+32]*lk2[t+32];
    #pragma unroll
    for (int o = 16; o; o >>= 1) {
        a += __shfl_xor_sync(0xffffffffu, a, o);
        b += __shfl_xor_sync(0xffffffffu, b, o);
    }
    if (t == 0) out[0] = expf(a) - expf(b) + LAMBDA_INIT;
}

// dual softmax + combine -> fp16 probs
__global__ void softmax_combine(const float* __restrict__ s12,
                                const float* __restrict__ lamp,
                                ushort4* __restrict__ ph)
{
    int gw   = (blockIdx.x*blockDim.x + threadIdx.x) >> 5;
    int lane = threadIdx.x & 31;
    if (gw >= NB*NH*NR) return;
    const float4* r1 = (const float4*)(s12 + (long long)gw * NR);
    const float4* r2 = (const float4*)(s12 + (long long)SSZ + (long long)gw * NR);
    float4 v1[4], v2[4];
    float m1 = -1e30f, m2 = -1e30f;
    #pragma unroll
    for (int i = 0; i < 4; i++) {
        v1[i] = r1[lane + 32*i]; v2[i] = r2[lane + 32*i];
        m1 = fmaxf(m1, fmaxf(fmaxf(v1[i].x, v1[i].y), fmaxf(v1[i].z, v1[i].w)));
        m2 = fmaxf(m2, fmaxf(fmaxf(v2[i].x, v2[i].y), fmaxf(v2[i].z, v2[i].w)));
    }
    #pragma unroll
    for (int o = 16; o; o >>= 1) {
        m1 = fmaxf(m1, __shfl_xor_sync(0xffffffffu, m1, o));
        m2 = fmaxf(m2, __shfl_xor_sync(0xffffffffu, m2, o));
    }
    float a1 = 0.f, a2 = 0.f;
    #pragma unroll
    for (int i = 0; i < 4; i++) {
        v1[i].x = __expf(v1[i].x-m1); v1[i].y = __expf(v1[i].y-m1);
        v1[i].z = __expf(v1[i].z-m1); v1[i].w = __expf(v1[i].w-m1);
        v2[i].x = __expf(v2[i].x-m2); v2[i].y = __expf(v2[i].y-m2);
        v2[i].z = __expf(v2[i].z-m2); v2[i].w = __expf(v2[i].w-m2);
        a1 += v1[i].x+v1[i].y+v1[i].z+v1[i].w;
        a2 += v2[i].x+v2[i].y+v2[i].z+v2[i].w;
    }
    #pragma unroll
    for (int o = 16; o; o >>= 1) {
        a1 += __shfl_xor_sync(0xffffffffu, a1, o);
        a2 += __shfl_xor_sync(0xffffffffu, a2, o);
    }
    float is1 = 1.f/a1, is2 = lamp[0]/a2;
    #pragma unroll
    for (int i = 0; i < 4; i++) {
        ushort4 h;
        h.x = h1(v1[i].x*is1 - v2[i].x*is2);
        h.y = h1(v1[i].y*is1 - v2[i].y*is2);
        h.z = h1(v1[i].z*is1 - v2[i].z*is2);
        h.w = h1(v1[i].w*is1 - v2[i].w*is2);
        ph[(long long)gw*128 + lane + 32*i] = h;
    }
}

// upsample 512 -> 4096
__global__ void upsample_kernel(const float4* __restrict__ lr, float4* __restrict__ out)
{
    int idx = blockIdx.x*blockDim.x + threadIdx.x;
    if (idx >= NB*NL*NC/4) return;
    int c4 = idx & 255, j = (idx >> 8) & (NL-1), b = idx >> 20;
    float coords = fminf(fmaxf(((float)j + 0.5f)*0.125f - 0.5f, 0.f), 511.f);
    int lo = (int)coords;
    int hi = min(lo + 1, 511);
    float w = coords - (float)lo, w0 = 1.f - w;
    long long base = (long long)b * NR * 256;
    float4 a = lr[base + (long long)lo*256 + c4];
    float4 c = lr[base + (long long)hi*256 + c4];
    float4 o;
    o.x = a.x*w0 + c.x*w; o.y = a.y*w0 + c.y*w;
    o.z = a.z*w0 + c.z*w; o.w = a.w*w0 + c.w*w;
    out[idx] = o;
}

// ======================= host launcher =======================================
extern "C" void kernel_launch(void* const* d_in, const int* in_sizes, int n_in,
                              void* d_out, int out_size)
{
    const float* x   = (const float*)d_in[0];
    const float* Wq  = (const float*)d_in[1];
    const float* Wk  = (const float*)d_in[2];
    const float* Wv  = (const float*)d_in[3];
    const float* Wo  = (const float*)d_in[4];
    const float* qw  = (const float*)d_in[5];
    const float* kw  = (const float*)d_in[6];
    const float* hw  = (const float*)d_in[7];
    const float* lq1 = (const float*)d_in[8];
    const float* lk1 = (const float*)d_in[9];
    const float* lq2 = (const float*)d_in[10];
    const float* lk2 = (const float*)d_in[11];

    float* full_out = (float*)d_out;
    float* lowrank  = full_out + (size_t)NB*NL*NC;

    #define GS(p, s) cudaGetSymbolAddress((void**)&p, s)
    __half *xd,*W,*Wo_,*q12,*k12,*vt,*pp,*y;
    float *s12,*lam;
    GS(xd,g_xd); GS(W,g_W); GS(Wo_,g_Wo);
    GS(q12,g_q12); GS(k12,g_k12); GS(vt,g_vt);
    GS(s12,g_s12); GS(pp,g_p); GS(y,g_y); GS(lam,g_lam);
    #undef GS

    cudaFuncSetAttribute(gemm_mma, cudaFuncAttributeMaxDynamicSharedMemorySize, GEMM_SMEM);

    // 1. downsample + fp16; weights fp16; lambda
    downsample_h<<<(NB*NR*NC/4 + 255)/256, 256>>>((const float4*)x, (ushort4*)xd);
    dim3 gcv((NC*NC/4 + 255)/256, 4);
    convert4<<<gcv, 256>>>((const float4*)Wq, (const float4*)Wk,
                           (const float4*)Wv, (const float4*)Wo,
                           (ushort4*)W, (ushort4*)Wo_);
    lambda_kernel<<<1, 32>>>(lq1, lk1, lq2, lk2, lam);

    // 2. QKV projections with fused normrope (z<2) / v-transpose (z=2) epilogues
    dim3 gqkv(NC/128, (NB*NR)/128, 3);
    gemm_mma<<<gqkv, 256, GEMM_SMEM>>>(xd, W, nullptr, NB*NR, NC, NC,
        0, (long long)NC*NC, 0, 1.f, 3, qw, kw);

    // 3. both score GEMMs in one launch (z in [0,64) spans s1|s2)
    dim3 gsc(NR/128, NR/128, 2*NB*NH);
    gemm_mma<<<gsc, 256, GEMM_SMEM>>>(q12, k12, s12, NR, NR, ND,
        (long long)NR*ND, (long long)NR*ND, (long long)NR*NR, 0.125f, 0, nullptr, nullptr);

    // 4. dual softmax + combine -> fp16 probs
    softmax_combine<<<(NB*NH*NR*32 + 255)/256, 256>>>(s12, lam, (ushort4*)pp);

    // 5. PV GEMM with fused head rmsnorm -> g_y
    dim3 gpv(1, NR/128, NB*NH);
    gemm_mma<<<gpv, 256, GEMM_SMEM>>>(pp, vt, nullptr, NR, 128, NR,
        (long long)NR*NR, (long long)128*NR, 0, 1.f, 2, hw, nullptr);

    // 6. Wo projection + fused silu -> lowrank_out
    dim3 gwo(NC/128, (NB*NR)/128, 1);
    gemm_mma<<<gwo, 256, GEMM_SMEM>>>(y, Wo_, lowrank, NB*NR, NC, NC,
        0, 0, 0, 1.f, 1, nullptr, nullptr);

    // 7. upsample -> full_out
    upsample_kernel<<<(NB*NL*NC/4 + 255)/256, 256>>>((const float4*)lowrank, (float4*)full_out);
}

// round 10
// speedup vs baseline: 5.4205x; 1.1736x over previous
#include <cuda_runtime.h>
#include <cuda_fp16.h>
#include <math.h>
#include <stdint.h>

#define NB 4
#define NL 4096
#define NC 1024
#define NH 8
#define NR 512
#define ND 64
#define LAMBDA_INIT 0.8f
#define EPS 1e-6f

#define SZQ   (NB*NH*NR*ND)
#define SSZ   (NB*NH*NR*NR)

// ======================= device scratch (no allocs allowed) ==================
__device__ __half g_xd [NB*NR*NC];
__device__ __half g_W  [3*NC*NC];          // Wq,Wk,Wv
__device__ __half g_Wo [NC*NC];
__device__ __half g_q12[2*SZQ];
__device__ __half g_k12[2*SZQ];
__device__ __half g_vt [NB*NH*128*NR];
__device__ float  g_s12[2*SSZ];
__device__ __half g_p  [SSZ];
__device__ __half g_y  [NB*NR*NC];
__device__ float  g_lam[1];

// ======================= asm helpers =========================================
__device__ __forceinline__ uint32_t smem_u32(const void* p){
    uint32_t a;
    asm("{ .reg .u64 t; cvta.to.shared.u64 t, %1; cvt.u32.u64 %0, t; }" : "=r"(a) : "l"(p));
    return a;
}
__device__ __forceinline__ void cpa16(uint32_t d, const void* s){
    asm volatile("cp.async.cg.shared.global [%0], [%1], 16;" :: "r"(d), "l"(s));
}
#define CP_COMMIT() asm volatile("cp.async.commit_group;" ::: "memory")
#define CP_WAIT0()  asm volatile("cp.async.wait_group 0;" ::: "memory")
#define CP_WAIT1()  asm volatile("cp.async.wait_group 1;" ::: "memory")

__device__ __forceinline__ void mma16816(float* c,
    uint32_t a0, uint32_t a1, uint32_t a2, uint32_t a3, uint32_t b0, uint32_t b1)
{
    asm volatile(
        "mma.sync.aligned.m16n8k16.row.col.f32.f16.f16.f32 "
        "{%0,%1,%2,%3}, {%4,%5,%6,%7}, {%8,%9}, {%0,%1,%2,%3};"
        : "+f"(c[0]), "+f"(c[1]), "+f"(c[2]), "+f"(c[3])
        : "r"(a0), "r"(a1), "r"(a2), "r"(a3), "r"(b0), "r"(b1));
}
#define LDSM4(r0,r1,r2,r3, addr) \
    asm volatile("ldmatrix.sync.aligned.m8n8.x4.shared.b16 {%0,%1,%2,%3}, [%4];" \
        : "=r"(r0),"=r"(r1),"=r"(r2),"=r"(r3) : "r"(addr))

__device__ __forceinline__ unsigned short h1(float v){
    return __half_as_ushort(__float2half_rn(v));
}

// ======================= HMMA fp16 batched NT GEMM ===========================
// BK=64, rows 144B (128B data + 16B pad), 3-stage cp.async, 2 CTAs/SM.
// mode 0: C = alpha*acc   1: silu   2: PV headnorm->g_y   3: QKV fused epilogue
#define ROW_B   144
#define TILE_B  (128*ROW_B)          // 18432
#define STG_B   (2*TILE_B)           // A+B = 36864
#define GEMM_SMEM (3*STG_B)          // 110592 -> 2 CTAs/SM (221184 <= 228KB)

__device__ __forceinline__ void ld_stage(uint32_t sbase, int tid, long long c64,
    const __half* Ab, const __half* Bb, int K)
{
    int seg = tid & 7;
    #pragma unroll
    for (int it = 0; it < 8; it++) {
        int i = tid + it*256;
        int r = (i >> 3) & 127;
        const __half* src = (it < 4) ? Ab : Bb;
        cpa16(sbase + (it >> 2)*TILE_B + r*ROW_B + seg*16,
              src + (long long)r*K + c64 + seg*8);
    }
    CP_COMMIT();
}

__global__ __launch_bounds__(256, 2)
void gemm_mma(const __half* __restrict__ A, const __half* __restrict__ B,
              float* __restrict__ C, int M, int N, int K,
              long long sA, long long sB, long long sC, float alpha, int mode,
              const float* __restrict__ w1, const float* __restrict__ w2)
{
    extern __shared__ char sm[];
    uint32_t sb = smem_u32(sm);
    const int tid  = threadIdx.x;
    const int wid  = tid >> 5, lane = tid & 31;
    const int gid  = lane >> 2, tig = lane & 3;
    const int wm   = (wid & 1) * 64;
    const int wn   = (wid >> 1) * 32;
    const int bm   = blockIdx.y * 128, bn = blockIdx.x * 128;
    const int z    = blockIdx.z;

    const __half* Ab = A + z*sA + (long long)bm*K;
    const __half* Bb = B + z*sB + (long long)bn*K;

    const int a_row = (lane & 7) + ((lane & 8)  ? 8 : 0);
    const int a_col = (lane & 16) ? 16 : 0;
    const int b_row = (lane & 7) + ((lane & 16) ? 8 : 0);
    const int b_col = (lane & 8)  ? 16 : 0;

    float acc[4][4][4];
    #pragma unroll
    for (int mi = 0; mi < 4; mi++)
        #pragma unroll
        for (int ni = 0; ni < 4; ni++)
            #pragma unroll
            for (int t = 0; t < 4; t++) acc[mi][ni][t] = 0.f;

    const int nch = K >> 6;
    ld_stage(sb, tid, 0, Ab, Bb, K);
    if (nch > 1) ld_stage(sb + STG_B, tid, 64, Ab, Bb, K);

    for (int c = 0; c < nch; c++) {
        if (c + 1 < nch) CP_WAIT1(); else CP_WAIT0();
        __syncthreads();                       // stage c ready; stage c-1 consumed
        if (c + 2 < nch)
            ld_stage(sb + ((c + 2) % 3)*STG_B, tid, (long long)(c + 2)*64, Ab, Bb, K);

        const uint32_t p  = sb + (c % 3)*STG_B;
        const uint32_t pA = p, pB = p + TILE_B;

        #pragma unroll
        for (int kk = 0; kk < 4; kk++) {
            const int ko = kk*32;              // 16 fp16 cols = 32 bytes
            uint32_t bh[4][2];
            #pragma unroll
            for (int nj = 0; nj < 2; nj++) {
                uint32_t bd = pB + (wn + nj*16 + b_row)*ROW_B + ko + b_col;
                LDSM4(bh[2*nj][0], bh[2*nj][1], bh[2*nj+1][0], bh[2*nj+1][1], bd);
            }
            #pragma unroll
            for (int mi = 0; mi < 4; mi++) {
                uint32_t ah[4];
                uint32_t ad = pA + (wm + mi*16 + a_row)*ROW_B + ko + a_col;
                LDSM4(ah[0], ah[1], ah[2], ah[3], ad);
                #pragma unroll
                for (int ni = 0; ni < 4; ni++)
                    mma16816(acc[mi][ni], ah[0], ah[1], ah[2], ah[3],
                             bh[ni][0], bh[ni][1]);
            }
        }
    }

    if (mode == 0 || mode == 1) {
        float* Cb = C + z*sC;
        #pragma unroll
        for (int mi = 0; mi < 4; mi++) {
            #pragma unroll
            for (int ni = 0; ni < 4; ni++) {
                int row = bm + wm + mi*16 + gid;
                int col = bn + wn + ni*8 + tig*2;
                float v0 = acc[mi][ni][0]*alpha, v1 = acc[mi][ni][1]*alpha;
                float v2 = acc[mi][ni][2]*alpha, v3 = acc[mi][ni][3]*alpha;
                if (mode == 1) {
                    v0 /= (1.f + __expf(-v0)); v1 /= (1.f + __expf(-v1));
                    v2 /= (1.f + __expf(-v2)); v3 /= (1.f + __expf(-v3));
                }
                *(float2*)&Cb[(long long)row*N + col]       = make_float2(v0, v1);
                *(float2*)&Cb[(long long)(row + 8)*N + col] = make_float2(v2, v3);
            }
        }
        return;
    }

    // ---------- stage accumulators to smem (row-major, or transposed for v) ---
    __syncthreads();                            // mainloop smem reads done
    float* esm = (float*)sm;                    // 128 x 132 floats
    const bool vtr = (mode == 3 && z == 2);
    #pragma unroll
    for (int mi = 0; mi < 4; mi++) {
        #pragma unroll
        for (int ni = 0; ni < 4; ni++) {
            int r0 = wm + mi*16 + gid;
            int cc = wn + ni*8 + tig*2;
            if (vtr) {
                esm[cc*132 + r0]         = acc[mi][ni][0];
                esm[(cc+1)*132 + r0]     = acc[mi][ni][1];
                esm[cc*132 + r0 + 8]     = acc[mi][ni][2];
                esm[(cc+1)*132 + r0 + 8] = acc[mi][ni][3];
            } else {
                esm[r0*132 + cc]         = acc[mi][ni][0];
                esm[r0*132 + cc + 1]     = acc[mi][ni][1];
                esm[(r0+8)*132 + cc]     = acc[mi][ni][2];
                esm[(r0+8)*132 + cc + 1] = acc[mi][ni][3];
            }
        }
    }
    __syncthreads();

    if (mode == 2) {
        // fused head rmsnorm (PV): z = b*8+h
        const int b = z >> 3, h = z & 7;
        for (int r = wid; r < 128; r += 8) {
            float4 vv = *(float4*)&esm[r*132 + lane*4];
            float ssq = vv.x*vv.x + vv.y*vv.y + vv.z*vv.z + vv.w*vv.w;
            #pragma unroll
            for (int o = 16; o; o >>= 1) ssq += __shfl_xor_sync(0xffffffffu, ssq, o);
            float inv = (1.f - LAMBDA_INIT) * rsqrtf(ssq*(1.f/128.f) + EPS);
            float4 w = ((const float4*)w1)[lane];
            ushort4 hh;
            hh.x = h1(vv.x*inv*w.x); hh.y = h1(vv.y*inv*w.y);
            hh.z = h1(vv.z*inv*w.z); hh.w = h1(vv.w*inv*w.w);
            int i = bm + r;
            long long o4 = (long long)(b*NR + i)*256 + h*32 + lane;
            ((ushort4*)g_y)[o4] = hh;
        }
        return;
    }

    // ---------- mode 3: fused QKV epilogue ------------------------------------
    const int h = blockIdx.x;              // tile cols = one head
    if (z < 2) {
        // rmsnorm(64) + rope(pos=h) + fp16 -> q12 / k12
        const float* w = z ? w2 : w1;
        const int gidx = lane & 15, sgi = lane >> 4;
        const int dmb = (gidx & 7) * 4;
        float4 wv = ((const float4*)w)[gidx];
        float sn[4], cs[4];
        #pragma unroll
        for (int j = 0; j < 4; j++) {
            float f = exp2f(-0.41524101186351494f * (float)(dmb + j));
            __sincosf((float)h * f, &sn[j], &cs[j]);
        }
        __half* dh = (z == 0 ? g_q12 : g_k12) + (long long)sgi*SZQ;
        const bool lo = (gidx & 8) == 0;
        for (int r = wid; r < 128; r += 8) {
            float4 xv = *(float4*)&esm[r*132 + sgi*64 + gidx*4];
            float ssq = xv.x*xv.x + xv.y*xv.y + xv.z*xv.z + xv.w*xv.w;
            #pragma unroll
            for (int o = 8; o; o >>= 1) ssq += __shfl_xor_sync(0xffffffffu, ssq, o);
            float inv = rsqrtf(ssq*(1.f/64.f) + EPS);
            float n0 = xv.x*inv*wv.x, n1 = xv.y*inv*wv.y;
            float n2 = xv.z*inv*wv.z, n3 = xv.w*inv*wv.w;
            float p0 = __shfl_xor_sync(0xffffffffu, n0, 8);
            float p1 = __shfl_xor_sync(0xffffffffu, n1, 8);
            float p2 = __shfl_xor_sync(0xffffffffu, n2, 8);
            float p3 = __shfl_xor_sync(0xffffffffu, n3, 8);
            ushort4 hh;
            hh.x = h1(lo ? n0*cs[0] - p0*sn[0] : p0*sn[0] + n0*cs[0]);
            hh.y = h1(lo ? n1*cs[1] - p1*sn[1] : p1*sn[1] + n1*cs[1]);
            hh.z = h1(lo ? n2*cs[2] - p2*sn[2] : p2*sn[2] + n2*cs[2]);
            hh.w = h1(lo ? n3*cs[3] - p3*sn[3] : p3*sn[3] + n3*cs[3]);
            int tok = bm + r, b = tok >> 9, il = tok & 511;
            long long off = ((long long)((b*NH + h)*NR) + il)*64 + gidx*4;
            *(ushort4*)(dh + off) = hh;
        }
    } else {
        // v: transposed fp16 write -> g_vt  (esm staged transposed)
        const int b = bm >> 9, ibase = bm & 511;
        const int bh = b*NH + h;
        #pragma unroll
        for (int it = 0; it < 32; it++) {
            int e = tid + it*256;
            int c = e >> 6, ip = e & 63, i = ip*2;
            float2 vv = *(float2*)&esm[c*132 + i];
            long long o = ((long long)(bh*128 + c))*NR + ibase + i;
            *(ushort2*)(g_vt + o) = make_ushort2(h1(vv.x), h1(vv.y));
        }
    }
}

// ======================= elementwise kernels =================================
__global__ void downsample_h(const float4* __restrict__ x, ushort4* __restrict__ xd)
{
    int idx = blockIdx.x*blockDim.x + threadIdx.x;
    if (idx >= NB*NR*NC/4) return;
    int c4 = idx & 255, bi = idx >> 8;
    int i = bi & (NR-1), b = bi >> 9;
    long long row = (long long)b*NL + 8*i + 3;
    float4 p = x[row*256 + c4], q = x[(row+1)*256 + c4];
    ushort4 h;
    h.x = h1(0.5f*(p.x+q.x)); h.y = h1(0.5f*(p.y+q.y));
    h.z = h1(0.5f*(p.z+q.z)); h.w = h1(0.5f*(p.w+q.w));
    xd[idx] = h;
}

__global__ void convert4(const float4* __restrict__ Wq, const float4* __restrict__ Wk,
                         const float4* __restrict__ Wv, const float4* __restrict__ Wo,
                         ushort4* __restrict__ w3, ushort4* __restrict__ wo)
{
    int idx = blockIdx.x*blockDim.x + threadIdx.x;
    if (idx >= NC*NC/4) return;
    const float4* s; ushort4* d; int off = 0;
    switch (blockIdx.y) {
        case 0: s = Wq; d = w3; off = 0;          break;
        case 1: s = Wk; d = w3; off = NC*NC/4;    break;
        case 2: s = Wv; d = w3; off = 2*(NC*NC/4);break;
        default:s = Wo; d = wo; off = 0;          break;
    }
    float4 v = s[idx];
    ushort4 h;
    h.x = h1(v.x); h.y = h1(v.y); h.z = h1(v.z); h.w = h1(v.w);
    d[off + idx] = h;
}

__global__ void lambda_kernel(const float* lq1, const float* lk1,
                              const float* lq2, const float* lk2, float* out)
{
    int t = threadIdx.x;
    float a = lq1[t]*lk1[t] + lq1[t+32]*lk1[t+32];
    float b = lq2[t]*lk2[t] + lq2[t+32]*lk2[t+32];
    #pragma unroll
    for (int o = 16; o; o >>= 1) {
        a += __shfl_xor_sync(0xffffffffu, a, o);
        b += __shfl_xor_sync(0xffffffffu, b, o);
    }
    if (t == 0) out[0] = expf(a) - expf(b) + LAMBDA_INIT;
}

// dual softmax + combine -> fp16 probs
__global__ void softmax_combine(const float* __restrict__ s12,
                                const float* __restrict__ lamp,
                                ushort4* __restrict__ ph)
{
    int gw   = (blockIdx.x*blockDim.x + threadIdx.x) >> 5;
    int lane = threadIdx.x & 31;
    if (gw >= NB*NH*NR) return;
    const float4* r1 = (const float4*)(s12 + (long long)gw * NR);
    const float4* r2 = (const float4*)(s12 + (long long)SSZ + (long long)gw * NR);
    float4 v1[4], v2[4];
    float m1 = -1e30f, m2 = -1e30f;
    #pragma unroll
    for (int i = 0; i < 4; i++) {
        v1[i] = r1[lane + 32*i]; v2[i] = r2[lane + 32*i];
        m1 = fmaxf(m1, fmaxf(fmaxf(v1[i].x, v1[i].y), fmaxf(v1[i].z, v1[i].w)));
        m2 = fmaxf(m2, fmaxf(fmaxf(v2[i].x, v2[i].y), fmaxf(v2[i].z, v2[i].w)));
    }
    #pragma unroll
    for (int o = 16; o; o >>= 1) {
        m1 = fmaxf(m1, __shfl_xor_sync(0xffffffffu, m1, o));
        m2 = fmaxf(m2, __shfl_xor_sync(0xffffffffu, m2, o));
    }
    float a1 = 0.f, a2 = 0.f;
    #pragma unroll
    for (int i = 0; i < 4; i++) {
        v1[i].x = __expf(v1[i].x-m1); v1[i].y = __expf(v1[i].y-m1);
        v1[i].z = __expf(v1[i].z-m1); v1[i].w = __expf(v1[i].w-m1);
        v2[i].x = __expf(v2[i].x-m2); v2[i].y = __expf(v2[i].y-m2);
        v2[i].z = __expf(v2[i].z-m2); v2[i].w = __expf(v2[i].w-m2);
        a1 += v1[i].x+v1[i].y+v1[i].z+v1[i].w;
        a2 += v2[i].x+v2[i].y+v2[i].z+v2[i].w;
    }
    #pragma unroll
    for (int o = 16; o; o >>= 1) {
        a1 += __shfl_xor_sync(0xffffffffu, a1, o);
        a2 += __shfl_xor_sync(0xffffffffu, a2, o);
    }
    float is1 = 1.f/a1, is2 = lamp[0]/a2;
    #pragma unroll
    for (int i = 0; i < 4; i++) {
        ushort4 h;
        h.x = h1(v1[i].x*is1 - v2[i].x*is2);
        h.y = h1(v1[i].y*is1 - v2[i].y*is2);
        h.z = h1(v1[i].z*is1 - v2[i].z*is2);
        h.w = h1(v1[i].w*is1 - v2[i].w*is2);
        ph[(long long)gw*128 + lane + 32*i] = h;
    }
}

// upsample 512 -> 4096
__global__ void upsample_kernel(const float4* __restrict__ lr, float4* __restrict__ out)
{
    int idx = blockIdx.x*blockDim.x + threadIdx.x;
    if (idx >= NB*NL*NC/4) return;
    int c4 = idx & 255, j = (idx >> 8) & (NL-1), b = idx >> 20;
    float coords = fminf(fmaxf(((float)j + 0.5f)*0.125f - 0.5f, 0.f), 511.f);
    int lo = (int)coords;
    int hi = min(lo + 1, 511);
    float w = coords - (float)lo, w0 = 1.f - w;
    long long base = (long long)b * NR * 256;
    float4 a = lr[base + (long long)lo*256 + c4];
    float4 c = lr[base + (long long)hi*256 + c4];
    float4 o;
    o.x = a.x*w0 + c.x*w; o.y = a.y*w0 + c.y*w;
    o.z = a.z*w0 + c.z*w; o.w = a.w*w0 + c.w*w;
    out[idx] = o;
}

// ======================= host launcher =======================================
extern "C" void kernel_launch(void* const* d_in, const int* in_sizes, int n_in,
                              void* d_out, int out_size)
{
    const float* x   = (const float*)d_in[0];
    const float* Wq  = (const float*)d_in[1];
    const float* Wk  = (const float*)d_in[2];
    const float* Wv  = (const float*)d_in[3];
    const float* Wo  = (const float*)d_in[4];
    const float* qw  = (const float*)d_in[5];
    const float* kw  = (const float*)d_in[6];
    const float* hw  = (const float*)d_in[7];
    const float* lq1 = (const float*)d_in[8];
    const float* lk1 = (const float*)d_in[9];
    const float* lq2 = (const float*)d_in[10];
    const float* lk2 = (const float*)d_in[11];

    float* full_out = (float*)d_out;
    float* lowrank  = full_out + (size_t)NB*NL*NC;

    #define GS(p, s) cudaGetSymbolAddress((void**)&p, s)
    __half *xd,*W,*Wo_,*q12,*k12,*vt,*pp,*y;
    float *s12,*lam;
    GS(xd,g_xd); GS(W,g_W); GS(Wo_,g_Wo);
    GS(q12,g_q12); GS(k12,g_k12); GS(vt,g_vt);
    GS(s12,g_s12); GS(pp,g_p); GS(y,g_y); GS(lam,g_lam);
    #undef GS

    cudaFuncSetAttribute(gemm_mma, cudaFuncAttributeMaxDynamicSharedMemorySize, GEMM_SMEM);

    // 1. downsample + fp16; weights fp16; lambda
    downsample_h<<<(NB*NR*NC/4 + 255)/256, 256>>>((const float4*)x, (ushort4*)xd);
    dim3 gcv((NC*NC/4 + 255)/256, 4);
    convert4<<<gcv, 256>>>((const float4*)Wq, (const float4*)Wk,
                           (const float4*)Wv, (const float4*)Wo,
                           (ushort4*)W, (ushort4*)Wo_);
    lambda_kernel<<<1, 32>>>(lq1, lk1, lq2, lk2, lam);

    // 2. QKV projections with fused normrope (z<2) / v-transpose (z=2) epilogues
    dim3 gqkv(NC/128, (NB*NR)/128, 3);
    gemm_mma<<<gqkv, 256, GEMM_SMEM>>>(xd, W, nullptr, NB*NR, NC, NC,
        0, (long long)NC*NC, 0, 1.f, 3, qw, kw);

    // 3. both score GEMMs in one launch (z in [0,64) spans s1|s2)
    dim3 gsc(NR/128, NR/128, 2*NB*NH);
    gemm_mma<<<gsc, 256, GEMM_SMEM>>>(q12, k12, s12, NR, NR, ND,
        (long long)NR*ND, (long long)NR*ND, (long long)NR*NR, 0.125f, 0, nullptr, nullptr);

    // 4. dual softmax + combine -> fp16 probs
    softmax_combine<<<(NB*NH*NR*32 + 255)/256, 256>>>(s12, lam, (ushort4*)pp);

    // 5. PV GEMM with fused head rmsnorm -> g_y
    dim3 gpv(1, NR/128, NB*NH);
    gemm_mma<<<gpv, 256, GEMM_SMEM>>>(pp, vt, nullptr, NR, 128, NR,
        (long long)NR*NR, (long long)128*NR, 0, 1.f, 2, hw, nullptr);

    // 6. Wo projection + fused silu -> lowrank_out
    dim3 gwo(NC/128, (NB*NR)/128, 1);
    gemm_mma<<<gwo, 256, GEMM_SMEM>>>(y, Wo_, lowrank, NB*NR, NC, NC,
        0, 0, 0, 1.f, 1, nullptr, nullptr);

    // 7. upsample -> full_out
    upsample_kernel<<<(NB*NL*NC/4 + 255)/256, 256>>>((const float4*)lowrank, (float4*)full_out);
}